// round 12
// baseline (speedup 1.0000x reference)
#include <cuda_runtime.h>
#include <cuda_fp16.h>
#include <math.h>

#define BB 32
#define NN 16384
#define DD 64
#define SS 7
#define HH 128
#define TILE 128
#define TPB 256
#define TILES_PER_B (NN / TILE)   // 128

__device__ __align__(16) float g_P[DD*DD];
__device__ __align__(16) float g_slots[BB*SS*DD];
__device__ __align__(16) float g_h0[BB*DD];
__device__ __align__(16) float g_qp[BB*SS*DD];
__device__ __align__(16) float g_U[BB*SS*DD];
__device__ float g_Z[BB*SS];
__device__ __align__(16) float g_Sx[BB*DD];             // sum_n xn (for eps fold)
__device__ __align__(16) float g_gi[BB*SS*3*DD];        // GRU input gates
__device__ __align__(16) __half g_xn[(long)BB*NN*DD];   // 64 MB LN(x) cache

// ---- k_attn smem layout (bytes), TILE=128 ----
#define A_XN    0        // 128 rows * 72 halves = 18432 B
#define A_QPH   18432    // 8 * 72 halves = 1152 B
#define A_PT    19584    // 8 * 136 halves = 2176 B
#define A_PART  21760    // 2 * 64 * 8 fp32 = 4096 B
#define ATTN_SMEM_BYTES 25856

// ---- k_prep smem layout (floats) ----
#define P_IN  0           // 128 rows * 17 f4 = 8704 fl
#define P_OUT 8704        // 128 rows * 9 f4  = 4608 fl
#define P_G   13312
#define P_B   13376
#define PREP_SMEM_BYTES ((13440)*4)

// ---- k_upd2 smem layout (floats) ----
#define V_WHH 0           // 192*68 = 13056
#define V_GI  13056       // 1344
#define V_SL  14400       // 448
#define V_XB  14848       // 448
#define V_HID 15296       // 896
#define V_H   16192       // 64
#define V_GH  16256       // 192
#define V_M7  16448       // 8
#define V_R7  16456       // 8
#define UPD2_SMEM_BYTES ((16464)*4)

__device__ __forceinline__ unsigned pack_h2(float a, float b) {
    __half2 h = __float22half2_rn(make_float2(a, b));
    return *(unsigned*)&h;
}

#define LDSM_X4(a0,a1,a2,a3,addr) \
    asm volatile("ldmatrix.sync.aligned.m8n8.x4.shared.b16 {%0,%1,%2,%3}, [%4];" \
        : "=r"(a0),"=r"(a1),"=r"(a2),"=r"(a3) : "r"(addr))
#define LDSM_X4_T(a0,a1,a2,a3,addr) \
    asm volatile("ldmatrix.sync.aligned.m8n8.x4.trans.shared.b16 {%0,%1,%2,%3}, [%4];" \
        : "=r"(a0),"=r"(a1),"=r"(a2),"=r"(a3) : "r"(addr))
#define MMA16816(c0,c1,c2,c3,a0,a1,a2,a3,b0,b1) \
    asm volatile("mma.sync.aligned.m16n8k16.row.col.f32.f16.f16.f32 " \
        "{%0,%1,%2,%3}, {%4,%5,%6,%7}, {%8,%9}, {%0,%1,%2,%3};" \
        : "+f"(c0),"+f"(c1),"+f"(c2),"+f"(c3) \
        : "r"(a0),"r"(a1),"r"(a2),"r"(a3),"r"(b0),"r"(b1))
#define CP_ASYNC16(dst, src) \
    asm volatile("cp.async.cg.shared.global [%0], [%1], 16;" :: "r"(dst), "l"(src))
#define CP_COMMIT() asm volatile("cp.async.commit_group;" ::: "memory")
#define CP_WAIT(n)  asm volatile("cp.async.wait_group %0;" :: "n"(n) : "memory")

// ---------------------------------------------------------------------------
// k_setup: blocks 0..31 -> slots/h0 init + zero U,Z,Sx.  block 32 -> P=Wq^T Wk
// ---------------------------------------------------------------------------
__global__ void k_setup(const float* __restrict__ mu, const float* __restrict__ lsig,
                        const float* __restrict__ nslots, const float* __restrict__ nh,
                        const float* __restrict__ Wq, const float* __restrict__ Wk) {
    int blk = blockIdx.x, tid = threadIdx.x;
    if (blk < BB) {
        int b = blk;
        for (int i = tid; i < SS*DD; i += blockDim.x) {
            int d = i & (DD-1);
            float sg = __expf(lsig[d]);
            g_slots[b*SS*DD + i] = mu[d] + sg * nslots[b*SS*DD + i];
            g_U[b*SS*DD + i] = 0.f;
        }
        for (int d = tid; d < DD; d += blockDim.x) {
            float sg = __expf(lsig[d]);
            g_h0[b*DD + d] = mu[d] + sg * nh[b*DD + d];
            g_Sx[b*DD + d] = 0.f;
        }
        if (tid < SS) g_Z[b*SS + tid] = 0.f;
    } else {
        __shared__ float sq[DD*DD], sk[DD*DD];
        for (int i = tid; i < DD*DD; i += blockDim.x) { sq[i] = Wq[i]; sk[i] = Wk[i]; }
        __syncthreads();
        for (int i = tid; i < DD*DD; i += blockDim.x) {
            int dp = i >> 6, d = i & 63;
            float acc = 0.f;
            for (int e = 0; e < DD; e++) acc += sq[e*DD+dp] * sk[e*DD+d];
            g_P[i] = acc;
        }
    }
}

// ---------------------------------------------------------------------------
// k_prep: LN(inputs) -> g_xn (fp16) + per-batch column sums Sx
// ---------------------------------------------------------------------------
__global__ __launch_bounds__(256)
void k_prep(const float* __restrict__ x_in,
            const float* __restrict__ lg, const float* __restrict__ lb) {
    extern __shared__ __align__(16) float sp[];
    float4* s_in  = (float4*)(sp + P_IN);      // [128][17]
    uint4*  s_out = (uint4*)(sp + P_OUT);      // [128][9]
    float*  s_g   = sp + P_G;
    float*  s_b   = sp + P_B;
    int tid = threadIdx.x;
    long row_base = (long)blockIdx.x * 128;
    int b = blockIdx.x >> 7;                   // NN/128 = 128 blocks per batch

    if (tid < DD) { s_g[tid] = lg[tid]; s_b[tid] = lb[tid]; }
    const float4* gin = (const float4*)x_in + row_base*16;
#pragma unroll
    for (int jj = 0; jj < 8; jj++) {
        int li = jj*256 + tid;
        s_in[(li>>4)*17 + (li&15)] = gin[li];
    }
    __syncthreads();

    if (tid < 128) {
        const float4* xr = s_in + tid*17;
        float4 x[16];
#pragma unroll
        for (int j = 0; j < 16; j++) x[j] = xr[j];
        float sm = 0.f, sq = 0.f;
#pragma unroll
        for (int j = 0; j < 16; j++) {
            sm += x[j].x + x[j].y + x[j].z + x[j].w;
            sq += x[j].x*x[j].x + x[j].y*x[j].y + x[j].z*x[j].z + x[j].w*x[j].w;
        }
        float m = sm * (1.f/DD);
        float rstd = rsqrtf(sq*(1.f/DD) - m*m + 1e-5f);
#pragma unroll
        for (int j = 0; j < 8; j++) {
            float4 a = x[2*j], c = x[2*j+1];
            float n0 = (a.x-m)*rstd*s_g[8*j+0] + s_b[8*j+0];
            float n1 = (a.y-m)*rstd*s_g[8*j+1] + s_b[8*j+1];
            float n2 = (a.z-m)*rstd*s_g[8*j+2] + s_b[8*j+2];
            float n3 = (a.w-m)*rstd*s_g[8*j+3] + s_b[8*j+3];
            float n4 = (c.x-m)*rstd*s_g[8*j+4] + s_b[8*j+4];
            float n5 = (c.y-m)*rstd*s_g[8*j+5] + s_b[8*j+5];
            float n6 = (c.z-m)*rstd*s_g[8*j+6] + s_b[8*j+6];
            float n7 = (c.w-m)*rstd*s_g[8*j+7] + s_b[8*j+7];
            uint4 o;
            o.x = pack_h2(n0, n1);
            o.y = pack_h2(n2, n3);
            o.z = pack_h2(n4, n5);
            o.w = pack_h2(n6, n7);
            s_out[tid*9 + j] = o;
        }
    }
    __syncthreads();

    uint4* gout = (uint4*)g_xn + row_base*8;
#pragma unroll
    for (int jj = 0; jj < 4; jj++) {
        int li = jj*256 + tid;
        gout[li] = s_out[(li>>3)*9 + (li&7)];
    }
    // column sums of this block's 128 normalized rows (fp16-consistent)
    if (tid < DD) {
        const __half* hp = (const __half*)s_out;
        float acc = 0.f;
        for (int r = 0; r < 128; r++) acc += __half2float(hp[r*72 + tid]);
        atomicAdd(&g_Sx[b*DD + tid], acc);
    }
}

// ---------------------------------------------------------------------------
// k_qp0: q'[b,s,:] = scale * LN_slots(slots[b,s]) @ P
// ---------------------------------------------------------------------------
__global__ void k_qp0(const float* __restrict__ lsg, const float* __restrict__ lsb) {
    int b = blockIdx.x, tid = threadIdx.x;
    __shared__ float sl[SS*DD], sn[SS*DD], m7[SS], r7[SS];
    for (int i = tid; i < SS*DD; i += blockDim.x) sl[i] = g_slots[b*SS*DD+i];
    __syncthreads();
    if (tid < SS) {
        float sm = 0.f, sq = 0.f;
        for (int d = 0; d < DD; d++) { float v = sl[tid*DD+d]; sm += v; sq += v*v; }
        float m = sm * (1.f/DD);
        m7[tid] = m;
        r7[tid] = rsqrtf(sq*(1.f/DD) - m*m + 1e-5f);
    }
    __syncthreads();
    for (int i = tid; i < SS*DD; i += blockDim.x) {
        int s = i >> 6, d = i & 63;
        sn[i] = (sl[i]-m7[s])*r7[s]*lsg[d] + lsb[d];
    }
    __syncthreads();
    for (int o = tid; o < SS*DD; o += blockDim.x) {
        int s = o >> 6, d = o & 63;
        float acc = 0.f;
        for (int dp = 0; dp < DD; dp++) acc += sn[s*DD+dp] * g_P[dp*DD+d];
        g_qp[b*SS*DD+o] = 0.125f * acc;
    }
}

// ---------------------------------------------------------------------------
// k_attn (HMMA, TILE=128): cp.async copy -> GEMM1+softmax -> GEMM2 -> REDs
// ---------------------------------------------------------------------------
__global__ __launch_bounds__(TPB)
void k_attn() {
    extern __shared__ __align__(16) char smem[];
    __half* qph  = (__half*)(smem + A_QPH);     // [8][72]
    __half* pT   = (__half*)(smem + A_PT);      // [8][136]
    float*  part = (float*)(smem + A_PART);     // [2][64][8]

    int b   = blockIdx.x >> 7;                  // TILES_PER_B = 128
    int rb  = (blockIdx.x & (TILES_PER_B-1)) * TILE;
    int tid = threadIdx.x;
    int w   = tid >> 5, l = tid & 31;

    unsigned xn_sa = (unsigned)__cvta_generic_to_shared(smem + A_XN);

    // ---- phase 0: cp.async tile copy (1024 x 16B), q' staging overlaps ----
    {
        const uint4* gx = (const uint4*)g_xn + ((long)b*NN + rb)*8;
#pragma unroll
        for (int jj = 0; jj < 4; jj++) {
            int li = jj*256 + tid;              // 0..1023
            unsigned dst = xn_sa + (unsigned)(((li>>3)*9 + (li&7))*16);
            CP_ASYNC16(dst, gx + li);
        }
        CP_COMMIT();
        int n = tid >> 5, kp = tid & 31;
        float2 v = (n < 7) ? ((const float2*)(g_qp + b*SS*DD + n*DD))[kp]
                           : make_float2(0.f, 0.f);
        *(unsigned*)(qph + n*72 + kp*2) = pack_h2(v.x, v.y);
        CP_WAIT(0);
    }
    __syncthreads();

    int e   = 2*(l & 3);          // C-frag / B-frag k-pair col
    int gid = l >> 2;
    bool lastc = (l & 3) == 3;

    // ---- phase 1: GEMM1 (one 16-row m-tile per warp) + softmax ----
    float zacc0 = 0.f, zacc1 = 0.f;
    {
        int arow = (l & 15);
        int acol = (l >> 4) << 3;
        int r0 = w*16;
        float c0=0.f,c1=0.f,c2=0.f,c3=0.f;
#pragma unroll
        for (int kk = 0; kk < 4; kk++) {
            unsigned addr = xn_sa + (unsigned)(((r0 + arow)*72 + kk*16 + acol)*2);
            unsigned a0,a1,a2,a3;
            LDSM_X4(a0,a1,a2,a3, addr);
            unsigned b0 = *(const unsigned*)(qph + gid*72 + kk*16 + e);
            unsigned b1 = *(const unsigned*)(qph + gid*72 + kk*16 + e + 8);
            MMA16816(c0,c1,c2,c3, a0,a1,a2,a3, b0,b1);
        }
        int rA = r0 + gid, rB = rA + 8;
        float v1 = lastc ? -1e30f : c1;
        float v3 = lastc ? -1e30f : c3;
        float m0 = fmaxf(c0, v1), m1 = fmaxf(c2, v3);
        m0 = fmaxf(m0, __shfl_xor_sync(0xffffffffu, m0, 1));
        m0 = fmaxf(m0, __shfl_xor_sync(0xffffffffu, m0, 2));
        m1 = fmaxf(m1, __shfl_xor_sync(0xffffffffu, m1, 1));
        m1 = fmaxf(m1, __shfl_xor_sync(0xffffffffu, m1, 2));
        float e0 = __expf(c0 - m0), e1 = lastc ? 0.f : __expf(c1 - m0);
        float e2 = __expf(c2 - m1), e3 = lastc ? 0.f : __expf(c3 - m1);
        float s0 = e0 + e1, s1 = e2 + e3;
        s0 += __shfl_xor_sync(0xffffffffu, s0, 1);
        s0 += __shfl_xor_sync(0xffffffffu, s0, 2);
        s1 += __shfl_xor_sync(0xffffffffu, s1, 1);
        s1 += __shfl_xor_sync(0xffffffffu, s1, 2);
        float p0 = e0/s0, p1 = e1/s0, p2 = e2/s1, p3 = e3/s1;
        pT[e*136 + rA]     = __float2half_rn(p0);
        pT[(e+1)*136 + rA] = __float2half_rn(p1);
        pT[e*136 + rB]     = __float2half_rn(p2);
        pT[(e+1)*136 + rB] = __float2half_rn(p3);
        zacc0 += p0 + p2; zacc1 += p1 + p3;
    }
    zacc0 += __shfl_xor_sync(0xffffffffu, zacc0, 4);
    zacc0 += __shfl_xor_sync(0xffffffffu, zacc0, 8);
    zacc0 += __shfl_xor_sync(0xffffffffu, zacc0, 16);
    zacc1 += __shfl_xor_sync(0xffffffffu, zacc1, 4);
    zacc1 += __shfl_xor_sync(0xffffffffu, zacc1, 8);
    zacc1 += __shfl_xor_sync(0xffffffffu, zacc1, 16);
    if (l < 4) {
        atomicAdd(&g_Z[b*SS + 2*l], zacc0);
        if (l < 3) atomicAdd(&g_Z[b*SS + 2*l + 1], zacc1);
    }
    __syncthreads();

    // ---- phase 2: GEMM2  U^T[64x8] = xn^T @ P  (kh halves of 64 rows) ----
    {
        int mt = w & 3, kh = w >> 2;
        int d0 = mt*16;
        int R  = kh*64;
        float c0=0.f,c1=0.f,c2=0.f,c3=0.f;
        int trow = (l & 7) + ((l >> 4) << 3);
        int tcol = ((l >> 3) & 1) << 3;
#pragma unroll
        for (int kk = 0; kk < 4; kk++) {
            int k0 = R + kk*16;
            unsigned addr = xn_sa + (unsigned)(((k0 + trow)*72 + d0 + tcol)*2);
            unsigned a0,a1,a2,a3;
            LDSM_X4_T(a0,a1,a2,a3, addr);
            unsigned b0 = *(const unsigned*)(pT + gid*136 + k0 + e);
            unsigned b1 = *(const unsigned*)(pT + gid*136 + k0 + e + 8);
            MMA16816(c0,c1,c2,c3, a0,a1,a2,a3, b0,b1);
        }
        int dim = d0 + gid;
        float2* pp = (float2*)part;
        pp[kh*256 + dim*4 + (e>>1)]     = make_float2(c0, c1);
        pp[kh*256 + (dim+8)*4 + (e>>1)] = make_float2(c2, c3);
    }
    __syncthreads();
    // merge kh halves + global REDs
#pragma unroll
    for (int i = tid; i < 512; i += TPB) {
        int s = i & 7;
        if (s < 7) {
            int dim = i >> 3;
            float v = part[i] + part[512 + i];
            atomicAdd(&g_U[(b*SS + s)*DD + dim], v);
        }
    }
}

// ---------------------------------------------------------------------------
// k_upd1: per (b,s): updates = ((U + eps*Sx) . Wv^T)/(Z + N*eps), gi = ...
// ---------------------------------------------------------------------------
__global__ __launch_bounds__(192)
void k_upd1(const float* __restrict__ Wv,
            const float* __restrict__ w_ih, const float* __restrict__ b_ih) {
    int blk = blockIdx.x;           // 0..223
    int b = blk / SS, s = blk - b*SS;
    int tid = threadIdx.x;
    __shared__ float sU[DD], supd[DD];
    __shared__ float sZ;

    if (tid < DD) sU[tid] = g_U[(b*SS+s)*DD + tid] + 1e-8f * g_Sx[b*DD + tid];
    if (tid == 0) sZ = g_Z[b*SS+s] + 1.6384e-4f;   // + N*eps
    __syncthreads();

    if (tid < DD) {
        const float4* w = (const float4*)(Wv + tid*DD);
        const float4* u = (const float4*)sU;
        float a0=0,a1=0,a2=0,a3=0;
#pragma unroll
        for (int j = 0; j < 16; j++) {
            float4 a = u[j], c = w[j];
            a0 += a.x*c.x; a1 += a.y*c.y; a2 += a.z*c.z; a3 += a.w*c.w;
        }
        supd[tid] = ((a0+a1)+(a2+a3)) / sZ;
    }
    __syncthreads();

    {
        const float4* w = (const float4*)(w_ih + tid*DD);
        const float4* u = (const float4*)supd;
        float a0=b_ih[tid],a1=0,a2=0,a3=0;
#pragma unroll
        for (int j = 0; j < 16; j++) {
            float4 a = u[j], c = w[j];
            a0 += a.x*c.x; a1 += a.y*c.y; a2 += a.z*c.z; a3 += a.w*c.w;
        }
        g_gi[(b*SS+s)*3*DD + tid] = (a0+a1)+(a2+a3);
    }
}

// ---------------------------------------------------------------------------
// k_upd2: GRU over slots (whh staged) -> MLP -> slots + next q'
// ---------------------------------------------------------------------------
__global__ __launch_bounds__(256)
void k_upd2(const float* __restrict__ w_hh, const float* __restrict__ b_hh,
            const float* __restrict__ w1, const float* __restrict__ b1,
            const float* __restrict__ w2, const float* __restrict__ b2,
            const float* __restrict__ lsg, const float* __restrict__ lsb,
            const float* __restrict__ lmg, const float* __restrict__ lmb,
            float* __restrict__ dout, int last) {
    extern __shared__ __align__(16) float sm[];
    float* whh = sm + V_WHH;     // [192][68]
    float* gis = sm + V_GI;      // [7][192]
    float* sl  = sm + V_SL;      // [7][64]
    float* xb  = sm + V_XB;
    float* hid = sm + V_HID;     // [7][128]
    float* h   = sm + V_H;
    float* ghs = sm + V_GH;      // [192]
    float* m7  = sm + V_M7;
    float* r7  = sm + V_R7;

    int b = blockIdx.x, tid = threadIdx.x;

    for (int i = tid; i < 3*DD*DD; i += 256) { int r = i>>6, e = i&63; whh[r*68+e] = w_hh[i]; }
    for (int i = tid; i < SS*3*DD; i += 256) gis[i] = g_gi[b*SS*3*DD + i];
    if (tid < DD) h[tid] = g_h0[b*DD+tid];
    __syncthreads();

    for (int s = 0; s < SS; s++) {
        if (tid < 3*DD) {
            const float4* w = (const float4*)(whh + tid*68);
            const float4* hv = (const float4*)h;
            float a0=b_hh[tid],a1=0,a2=0,a3=0;
#pragma unroll
            for (int j = 0; j < 16; j++) {
                float4 c = w[j], a = hv[j];
                a0 += a.x*c.x; a1 += a.y*c.y; a2 += a.z*c.z; a3 += a.w*c.w;
            }
            ghs[tid] = (a0+a1)+(a2+a3);
        }
        __syncthreads();
        if (tid < DD) {
            float r = 1.f/(1.f + __expf(-(gis[s*192+tid]     + ghs[tid])));
            float z = 1.f/(1.f + __expf(-(gis[s*192+64+tid]  + ghs[64+tid])));
            float nx = gis[s*192+128+tid] + r*ghs[128+tid];
            float n = 1.f - 2.f/(__expf(2.f*nx) + 1.f);   // tanh
            float hn = (1.f-z)*n + z*h[tid];
            h[tid] = hn;
            sl[s*DD+tid] = hn;
        }
        __syncthreads();
    }

    if (tid < SS) {
        float smv = 0.f, sq = 0.f;
        for (int d = 0; d < DD; d++) { float v = sl[tid*DD+d]; smv += v; sq += v*v; }
        float m = smv*(1.f/DD);
        m7[tid] = m; r7[tid] = rsqrtf(sq*(1.f/DD) - m*m + 1e-5f);
    }
    __syncthreads();
    for (int i = tid; i < SS*DD; i += 256) {
        int s = i >> 6, d = i & 63;
        xb[i] = (sl[i]-m7[s])*r7[s]*lmg[d] + lmb[d];
    }
    __syncthreads();
    for (int o = tid; o < SS*HH; o += 256) {
        int s = o >> 7, hc = o & 127;
        const float4* w = (const float4*)(w1 + hc*DD);
        const float4* u = (const float4*)(xb + s*DD);
        float a0=b1[hc],a1=0,a2=0,a3=0;
#pragma unroll
        for (int j = 0; j < 16; j++) {
            float4 a = u[j], c = w[j];
            a0 += a.x*c.x; a1 += a.y*c.y; a2 += a.z*c.z; a3 += a.w*c.w;
        }
        hid[o] = fmaxf((a0+a1)+(a2+a3), 0.f);
    }
    __syncthreads();
    for (int o = tid; o < SS*DD; o += 256) {
        int s = o >> 6, d = o & 63;
        const float4* w = (const float4*)(w2 + d*HH);
        const float4* u = (const float4*)(hid + s*HH);
        float a0=b2[d],a1=0,a2=0,a3=0;
#pragma unroll
        for (int j = 0; j < 32; j++) {
            float4 a = u[j], c = w[j];
            a0 += a.x*c.x; a1 += a.y*c.y; a2 += a.z*c.z; a3 += a.w*c.w;
        }
        float v = sl[o] + (a0+a1)+(a2+a3);
        sl[o] = v;
        g_slots[b*SS*DD+o] = v;
        dout[b*SS*DD+o] = v;
    }
    __syncthreads();

    if (!last) {
        if (tid < SS) {
            float smv = 0.f, sq = 0.f;
            for (int d = 0; d < DD; d++) { float v = sl[tid*DD+d]; smv += v; sq += v*v; }
            float m = smv*(1.f/DD);
            m7[tid] = m; r7[tid] = rsqrtf(sq*(1.f/DD) - m*m + 1e-5f);
        }
        __syncthreads();
        for (int i = tid; i < SS*DD; i += 256) {
            int s = i >> 6, d = i & 63;
            xb[i] = (sl[i]-m7[s])*r7[s]*lsg[d] + lsb[d];
        }
        __syncthreads();
        for (int o = tid; o < SS*DD; o += 256) {
            int s = o >> 6, d = o & 63;
            float a0=0,a1=0,a2=0,a3=0;
#pragma unroll
            for (int dp = 0; dp < DD; dp += 4) {
                a0 += xb[s*DD+dp+0]*g_P[(dp+0)*DD+d];
                a1 += xb[s*DD+dp+1]*g_P[(dp+1)*DD+d];
                a2 += xb[s*DD+dp+2]*g_P[(dp+2)*DD+d];
                a3 += xb[s*DD+dp+3]*g_P[(dp+3)*DD+d];
            }
            g_qp[b*SS*DD+o] = 0.125f*((a0+a1)+(a2+a3));
            g_U[b*SS*DD+o] = 0.f;
        }
        if (tid < SS) g_Z[b*SS+tid] = 0.f;
    }
}

// ---------------------------------------------------------------------------
extern "C" void kernel_launch(void* const* d_in, const int* in_sizes, int n_in,
                              void* d_out, int out_size) {
    const float* inputs     = (const float*)d_in[0];
    const float* ln_in_g    = (const float*)d_in[1];
    const float* ln_in_b    = (const float*)d_in[2];
    const float* ln_slots_g = (const float*)d_in[3];
    const float* ln_slots_b = (const float*)d_in[4];
    const float* ln_mlp_g   = (const float*)d_in[5];
    const float* ln_mlp_b   = (const float*)d_in[6];
    const float* Wq         = (const float*)d_in[7];
    const float* Wk         = (const float*)d_in[8];
    const float* Wv         = (const float*)d_in[9];
    const float* mu         = (const float*)d_in[10];
    const float* lsig       = (const float*)d_in[11];
    const float* w_ih       = (const float*)d_in[12];
    const float* w_hh       = (const float*)d_in[13];
    const float* b_ih       = (const float*)d_in[14];
    const float* b_hh       = (const float*)d_in[15];
    const float* w1         = (const float*)d_in[16];
    const float* b1         = (const float*)d_in[17];
    const float* w2         = (const float*)d_in[18];
    const float* b2         = (const float*)d_in[19];
    const float* nslots     = (const float*)d_in[20];
    const float* nh         = (const float*)d_in[21];
    float* out = (float*)d_out;

    cudaFuncSetAttribute(k_prep,  cudaFuncAttributeMaxDynamicSharedMemorySize, PREP_SMEM_BYTES);
    cudaFuncSetAttribute(k_attn,  cudaFuncAttributeMaxDynamicSharedMemorySize, ATTN_SMEM_BYTES);
    cudaFuncSetAttribute(k_upd2,  cudaFuncAttributeMaxDynamicSharedMemorySize, UPD2_SMEM_BYTES);

    k_setup<<<BB+1, 256>>>(mu, lsig, nslots, nh, Wq, Wk);
    k_prep<<<(BB*NN)/128, 256, PREP_SMEM_BYTES>>>(inputs, ln_in_g, ln_in_b);
    k_qp0<<<BB, 256>>>(ln_slots_g, ln_slots_b);
    for (int it = 0; it < 3; it++) {
        k_attn<<<BB*TILES_PER_B, TPB, ATTN_SMEM_BYTES>>>();
        k_upd1<<<BB*SS, 192>>>(Wv, w_ih, b_ih);
        k_upd2<<<BB, 256, UPD2_SMEM_BYTES>>>(w_hh, b_hh, w1, b1, w2, b2,
                                             ln_slots_g, ln_slots_b, ln_mlp_g, ln_mlp_b,
                                             out, it == 2);
    }
}

// round 13
// speedup vs baseline: 2.1162x; 2.1162x over previous
#include <cuda_runtime.h>
#include <cuda_fp16.h>
#include <math.h>

#define BB 32
#define NN 16384
#define DD 64
#define SS 7
#define HH 128
#define TILE 128
#define NT 8                       // tiles per block
#define CHUNKS_PER_B 16            // 128 tiles / NT
#define TPB 256

__device__ __align__(16) float g_P[DD*DD];
__device__ __align__(16) float g_slots[BB*SS*DD];
__device__ __align__(16) float g_h0[BB*DD];
__device__ __align__(16) float g_qp[BB*SS*DD];
__device__ __align__(16) float g_U[BB*SS*DD];
__device__ float g_Z[BB*SS];
__device__ __align__(16) float g_Sx[BB*DD];             // sum_n xn (for eps fold)
__device__ __align__(16) float g_gi[BB*SS*3*DD];        // GRU input gates
__device__ __align__(16) __half g_xn[(long)BB*NN*DD];   // 64 MB LN(x) cache

// ---- k_attn smem layout (bytes): 2 x 128-row buffers ----
#define A_XN0   0        // 128 rows * 72 halves = 18432 B
#define A_XN1   18432
#define A_QPH   36864    // 8 * 72 halves = 1152 B
#define A_PT    38016    // 8 * 136 halves = 2176 B
#define A_PART  40192    // 2 * 64 * 8 fp32 = 4096 B
#define ATTN_SMEM_BYTES 44288

// ---- k_prep smem layout (floats) ----
#define P_IN  0           // 128 rows * 17 f4 = 8704 fl
#define P_OUT 8704        // 128 rows * 9 f4  = 4608 fl
#define P_G   13312
#define P_B   13376
#define PREP_SMEM_BYTES ((13440)*4)

// ---- k_upd2 smem layout (floats) ----
#define V_WHH 0           // 192*68 = 13056
#define V_GI  13056       // 1344
#define V_SL  14400       // 448
#define V_XB  14848       // 448
#define V_HID 15296       // 896
#define V_H   16192       // 64
#define V_GH  16256       // 192
#define V_M7  16448       // 8
#define V_R7  16456       // 8
#define UPD2_SMEM_BYTES ((16464)*4)

__device__ __forceinline__ unsigned pack_h2(float a, float b) {
    __half2 h = __float22half2_rn(make_float2(a, b));
    return *(unsigned*)&h;
}

#define LDSM_X4(a0,a1,a2,a3,addr) \
    asm volatile("ldmatrix.sync.aligned.m8n8.x4.shared.b16 {%0,%1,%2,%3}, [%4];" \
        : "=r"(a0),"=r"(a1),"=r"(a2),"=r"(a3) : "r"(addr))
#define LDSM_X4_T(a0,a1,a2,a3,addr) \
    asm volatile("ldmatrix.sync.aligned.m8n8.x4.trans.shared.b16 {%0,%1,%2,%3}, [%4];" \
        : "=r"(a0),"=r"(a1),"=r"(a2),"=r"(a3) : "r"(addr))
#define MMA16816(c0,c1,c2,c3,a0,a1,a2,a3,b0,b1) \
    asm volatile("mma.sync.aligned.m16n8k16.row.col.f32.f16.f16.f32 " \
        "{%0,%1,%2,%3}, {%4,%5,%6,%7}, {%8,%9}, {%0,%1,%2,%3};" \
        : "+f"(c0),"+f"(c1),"+f"(c2),"+f"(c3) \
        : "r"(a0),"r"(a1),"r"(a2),"r"(a3),"r"(b0),"r"(b1))
#define CP_ASYNC16(dst, src) \
    asm volatile("cp.async.cg.shared.global [%0], [%1], 16;" :: "r"(dst), "l"(src))
#define CP_COMMIT() asm volatile("cp.async.commit_group;" ::: "memory")
#define CP_WAIT(n)  asm volatile("cp.async.wait_group %0;" :: "n"(n) : "memory")

// ---------------------------------------------------------------------------
// k_setup: blocks 0..31 -> slots/h0 init + zero U,Z,Sx.  block 32 -> P=Wq^T Wk
// ---------------------------------------------------------------------------
__global__ void k_setup(const float* __restrict__ mu, const float* __restrict__ lsig,
                        const float* __restrict__ nslots, const float* __restrict__ nh,
                        const float* __restrict__ Wq, const float* __restrict__ Wk) {
    int blk = blockIdx.x, tid = threadIdx.x;
    if (blk < BB) {
        int b = blk;
        for (int i = tid; i < SS*DD; i += blockDim.x) {
            int d = i & (DD-1);
            float sg = __expf(lsig[d]);
            g_slots[b*SS*DD + i] = mu[d] + sg * nslots[b*SS*DD + i];
            g_U[b*SS*DD + i] = 0.f;
        }
        for (int d = tid; d < DD; d += blockDim.x) {
            float sg = __expf(lsig[d]);
            g_h0[b*DD + d] = mu[d] + sg * nh[b*DD + d];
            g_Sx[b*DD + d] = 0.f;
        }
        if (tid < SS) g_Z[b*SS + tid] = 0.f;
    } else {
        __shared__ float sq[DD*DD], sk[DD*DD];
        for (int i = tid; i < DD*DD; i += blockDim.x) { sq[i] = Wq[i]; sk[i] = Wk[i]; }
        __syncthreads();
        for (int i = tid; i < DD*DD; i += blockDim.x) {
            int dp = i >> 6, d = i & 63;
            float acc = 0.f;
            for (int e = 0; e < DD; e++) acc += sq[e*DD+dp] * sk[e*DD+d];
            g_P[i] = acc;
        }
    }
}

// ---------------------------------------------------------------------------
// k_prep: LN(inputs) -> g_xn (fp16) + per-batch column sums Sx
// ---------------------------------------------------------------------------
__global__ __launch_bounds__(256)
void k_prep(const float* __restrict__ x_in,
            const float* __restrict__ lg, const float* __restrict__ lb) {
    extern __shared__ __align__(16) float sp[];
    float4* s_in  = (float4*)(sp + P_IN);      // [128][17]
    uint4*  s_out = (uint4*)(sp + P_OUT);      // [128][9]
    float*  s_g   = sp + P_G;
    float*  s_b   = sp + P_B;
    int tid = threadIdx.x;
    long row_base = (long)blockIdx.x * 128;
    int b = blockIdx.x >> 7;                   // NN/128 = 128 blocks per batch

    if (tid < DD) { s_g[tid] = lg[tid]; s_b[tid] = lb[tid]; }
    const float4* gin = (const float4*)x_in + row_base*16;
#pragma unroll
    for (int jj = 0; jj < 8; jj++) {
        int li = jj*256 + tid;
        s_in[(li>>4)*17 + (li&15)] = gin[li];
    }
    __syncthreads();

    if (tid < 128) {
        const float4* xr = s_in + tid*17;
        float4 x[16];
#pragma unroll
        for (int j = 0; j < 16; j++) x[j] = xr[j];
        float sm = 0.f, sq = 0.f;
#pragma unroll
        for (int j = 0; j < 16; j++) {
            sm += x[j].x + x[j].y + x[j].z + x[j].w;
            sq += x[j].x*x[j].x + x[j].y*x[j].y + x[j].z*x[j].z + x[j].w*x[j].w;
        }
        float m = sm * (1.f/DD);
        float rstd = rsqrtf(sq*(1.f/DD) - m*m + 1e-5f);
#pragma unroll
        for (int j = 0; j < 8; j++) {
            float4 a = x[2*j], c = x[2*j+1];
            float n0 = (a.x-m)*rstd*s_g[8*j+0] + s_b[8*j+0];
            float n1 = (a.y-m)*rstd*s_g[8*j+1] + s_b[8*j+1];
            float n2 = (a.z-m)*rstd*s_g[8*j+2] + s_b[8*j+2];
            float n3 = (a.w-m)*rstd*s_g[8*j+3] + s_b[8*j+3];
            float n4 = (c.x-m)*rstd*s_g[8*j+4] + s_b[8*j+4];
            float n5 = (c.y-m)*rstd*s_g[8*j+5] + s_b[8*j+5];
            float n6 = (c.z-m)*rstd*s_g[8*j+6] + s_b[8*j+6];
            float n7 = (c.w-m)*rstd*s_g[8*j+7] + s_b[8*j+7];
            uint4 o;
            o.x = pack_h2(n0, n1);
            o.y = pack_h2(n2, n3);
            o.z = pack_h2(n4, n5);
            o.w = pack_h2(n6, n7);
            s_out[tid*9 + j] = o;
        }
    }
    __syncthreads();

    uint4* gout = (uint4*)g_xn + row_base*8;
#pragma unroll
    for (int jj = 0; jj < 4; jj++) {
        int li = jj*256 + tid;
        gout[li] = s_out[(li>>3)*9 + (li&7)];
    }
    // column sums of this block's 128 normalized rows (fp16-consistent)
    if (tid < DD) {
        const __half* hp = (const __half*)s_out;
        float acc = 0.f;
        for (int r = 0; r < 128; r++) acc += __half2float(hp[r*72 + tid]);
        atomicAdd(&g_Sx[b*DD + tid], acc);
    }
}

// ---------------------------------------------------------------------------
// k_qp0: q'[b,s,:] = scale * LN_slots(slots[b,s]) @ P
// ---------------------------------------------------------------------------
__global__ void k_qp0(const float* __restrict__ lsg, const float* __restrict__ lsb) {
    int b = blockIdx.x, tid = threadIdx.x;
    __shared__ float sl[SS*DD], sn[SS*DD], m7[SS], r7[SS];
    for (int i = tid; i < SS*DD; i += blockDim.x) sl[i] = g_slots[b*SS*DD+i];
    __syncthreads();
    if (tid < SS) {
        float sm = 0.f, sq = 0.f;
        for (int d = 0; d < DD; d++) { float v = sl[tid*DD+d]; sm += v; sq += v*v; }
        float m = sm * (1.f/DD);
        m7[tid] = m;
        r7[tid] = rsqrtf(sq*(1.f/DD) - m*m + 1e-5f);
    }
    __syncthreads();
    for (int i = tid; i < SS*DD; i += blockDim.x) {
        int s = i >> 6, d = i & 63;
        sn[i] = (sl[i]-m7[s])*r7[s]*lsg[d] + lsb[d];
    }
    __syncthreads();
    for (int o = tid; o < SS*DD; o += blockDim.x) {
        int s = o >> 6, d = o & 63;
        float acc = 0.f;
        for (int dp = 0; dp < DD; dp++) acc += sn[s*DD+dp] * g_P[dp*DD+d];
        g_qp[b*SS*DD+o] = 0.125f * acc;
    }
}

// ---------------------------------------------------------------------------
// k_attn: persistent 8-tile blocks, cp.async double buffer, C-regs accumulate
// across tiles, one atomic epilogue per block.
// ---------------------------------------------------------------------------
__global__ __launch_bounds__(TPB)
void k_attn() {
    extern __shared__ __align__(16) char smem[];
    __half* qph  = (__half*)(smem + A_QPH);     // [8][72]
    __half* pT   = (__half*)(smem + A_PT);      // [8][136]
    float*  part = (float*)(smem + A_PART);     // [2][64][8]

    int b     = blockIdx.x >> 4;                // CHUNKS_PER_B = 16
    int chunk = blockIdx.x & (CHUNKS_PER_B-1);
    int tid = threadIdx.x;
    int w   = tid >> 5, l = tid & 31;

    unsigned sbuf0 = (unsigned)__cvta_generic_to_shared(smem + A_XN0);
    unsigned sbuf1 = (unsigned)__cvta_generic_to_shared(smem + A_XN1);
    const uint4* gx = (const uint4*)g_xn + ((long)b*NN + (long)chunk*NT*TILE)*8;

    // issue tile i -> buffer (i&1): 1024 x 16B chunks
#define ISSUE_TILE(i) do { \
        unsigned dstb = ((i) & 1) ? sbuf1 : sbuf0; \
        const uint4* src = gx + (long)(i)*TILE*8; \
        _Pragma("unroll") \
        for (int jj = 0; jj < 4; jj++) { \
            int li = jj*256 + tid; \
            unsigned dst = dstb + (unsigned)(((li>>3)*9 + (li&7))*16); \
            CP_ASYNC16(dst, src + li); \
        } \
        CP_COMMIT(); \
    } while (0)

    ISSUE_TILE(0);
    ISSUE_TILE(1);

    // stage q' -> fp16 while copies are in flight
    {
        int n = tid >> 5, kp = tid & 31;
        float2 v = (n < 7) ? ((const float2*)(g_qp + b*SS*DD + n*DD))[kp]
                           : make_float2(0.f, 0.f);
        *(unsigned*)(qph + n*72 + kp*2) = pack_h2(v.x, v.y);
    }

    int e   = 2*(l & 3);          // C-frag / B-frag k-pair col
    int gid = l >> 2;
    bool lastc = (l & 3) == 3;

    // persistent accumulators
    float zacc0 = 0.f, zacc1 = 0.f;
    float u0 = 0.f, u1 = 0.f, u2 = 0.f, u3 = 0.f;   // GEMM2 C-fragments

    // phase-1 addressing (per warp: rows w*16..w*16+15)
    int arow = (l & 15);
    int acol = (l >> 4) << 3;
    int r0p1 = w*16;
    // phase-2 addressing
    int mt = w & 3, kh = w >> 2;
    int d0 = mt*16;
    int Rr = kh*64;
    int trow = (l & 7) + ((l >> 4) << 3);
    int tcol = ((l >> 3) & 1) << 3;

    for (int i = 0; i < NT; i++) {
        if (i == NT-1) { CP_WAIT(0); } else { CP_WAIT(1); }
        __syncthreads();
        unsigned xn_sa = (i & 1) ? sbuf1 : sbuf0;

        // ---- phase 1: GEMM1 + softmax -> pT ----
        {
            float c0=0.f,c1=0.f,c2=0.f,c3=0.f;
#pragma unroll
            for (int kk = 0; kk < 4; kk++) {
                unsigned addr = xn_sa + (unsigned)(((r0p1 + arow)*72 + kk*16 + acol)*2);
                unsigned a0,a1,a2,a3;
                LDSM_X4(a0,a1,a2,a3, addr);
                unsigned b0 = *(const unsigned*)(qph + gid*72 + kk*16 + e);
                unsigned b1 = *(const unsigned*)(qph + gid*72 + kk*16 + e + 8);
                MMA16816(c0,c1,c2,c3, a0,a1,a2,a3, b0,b1);
            }
            int rA = r0p1 + gid, rB = rA + 8;
            float v1 = lastc ? -1e30f : c1;
            float v3 = lastc ? -1e30f : c3;
            float m0 = fmaxf(c0, v1), m1 = fmaxf(c2, v3);
            m0 = fmaxf(m0, __shfl_xor_sync(0xffffffffu, m0, 1));
            m0 = fmaxf(m0, __shfl_xor_sync(0xffffffffu, m0, 2));
            m1 = fmaxf(m1, __shfl_xor_sync(0xffffffffu, m1, 1));
            m1 = fmaxf(m1, __shfl_xor_sync(0xffffffffu, m1, 2));
            float e0 = __expf(c0 - m0), e1 = lastc ? 0.f : __expf(c1 - m0);
            float e2 = __expf(c2 - m1), e3 = lastc ? 0.f : __expf(c3 - m1);
            float s0 = e0 + e1, s1 = e2 + e3;
            s0 += __shfl_xor_sync(0xffffffffu, s0, 1);
            s0 += __shfl_xor_sync(0xffffffffu, s0, 2);
            s1 += __shfl_xor_sync(0xffffffffu, s1, 1);
            s1 += __shfl_xor_sync(0xffffffffu, s1, 2);
            float p0 = e0/s0, p1 = e1/s0, p2 = e2/s1, p3 = e3/s1;
            pT[e*136 + rA]     = __float2half_rn(p0);
            pT[(e+1)*136 + rA] = __float2half_rn(p1);
            pT[e*136 + rB]     = __float2half_rn(p2);
            pT[(e+1)*136 + rB] = __float2half_rn(p3);
            zacc0 += p0 + p2; zacc1 += p1 + p3;
        }
        __syncthreads();

        // ---- phase 2: GEMM2 accumulate into persistent C-regs ----
#pragma unroll
        for (int kk = 0; kk < 4; kk++) {
            int k0 = Rr + kk*16;
            unsigned addr = xn_sa + (unsigned)(((k0 + trow)*72 + d0 + tcol)*2);
            unsigned a0,a1,a2,a3;
            LDSM_X4_T(a0,a1,a2,a3, addr);
            unsigned b0 = *(const unsigned*)(pT + gid*136 + k0 + e);
            unsigned b1 = *(const unsigned*)(pT + gid*136 + k0 + e + 8);
            MMA16816(u0,u1,u2,u3, a0,a1,a2,a3, b0,b1);
        }
        __syncthreads();   // all reads of this buffer + pT done

        if (i + 2 < NT) ISSUE_TILE(i + 2);
    }

    // ---- epilogue: Z atomics ----
    zacc0 += __shfl_xor_sync(0xffffffffu, zacc0, 4);
    zacc0 += __shfl_xor_sync(0xffffffffu, zacc0, 8);
    zacc0 += __shfl_xor_sync(0xffffffffu, zacc0, 16);
    zacc1 += __shfl_xor_sync(0xffffffffu, zacc1, 4);
    zacc1 += __shfl_xor_sync(0xffffffffu, zacc1, 8);
    zacc1 += __shfl_xor_sync(0xffffffffu, zacc1, 16);
    if (l < 4) {
        atomicAdd(&g_Z[b*SS + 2*l], zacc0);
        if (l < 3) atomicAdd(&g_Z[b*SS + 2*l + 1], zacc1);
    }

    // ---- epilogue: U partial store, merge, REDs ----
    {
        int dim = d0 + gid;
        float2* pp = (float2*)part;
        pp[kh*256 + dim*4 + (e>>1)]     = make_float2(u0, u1);
        pp[kh*256 + (dim+8)*4 + (e>>1)] = make_float2(u2, u3);
    }
    __syncthreads();
#pragma unroll
    for (int i = tid; i < 512; i += TPB) {
        int s = i & 7;
        if (s < 7) {
            int dim = i >> 3;
            float v = part[i] + part[512 + i];
            atomicAdd(&g_U[(b*SS + s)*DD + dim], v);
        }
    }
#undef ISSUE_TILE
}

// ---------------------------------------------------------------------------
// k_upd1: per (b,s): updates = ((U + eps*Sx) . Wv^T)/(Z + N*eps), gi = ...
// ---------------------------------------------------------------------------
__global__ __launch_bounds__(192)
void k_upd1(const float* __restrict__ Wv,
            const float* __restrict__ w_ih, const float* __restrict__ b_ih) {
    int blk = blockIdx.x;           // 0..223
    int b = blk / SS, s = blk - b*SS;
    int tid = threadIdx.x;
    __shared__ float sU[DD], supd[DD];
    __shared__ float sZ;

    if (tid < DD) sU[tid] = g_U[(b*SS+s)*DD + tid] + 1e-8f * g_Sx[b*DD + tid];
    if (tid == 0) sZ = g_Z[b*SS+s] + 1.6384e-4f;   // + N*eps
    __syncthreads();

    if (tid < DD) {
        const float4* w = (const float4*)(Wv + tid*DD);
        const float4* u = (const float4*)sU;
        float a0=0,a1=0,a2=0,a3=0;
#pragma unroll
        for (int j = 0; j < 16; j++) {
            float4 a = u[j], c = w[j];
            a0 += a.x*c.x; a1 += a.y*c.y; a2 += a.z*c.z; a3 += a.w*c.w;
        }
        supd[tid] = ((a0+a1)+(a2+a3)) / sZ;
    }
    __syncthreads();

    {
        const float4* w = (const float4*)(w_ih + tid*DD);
        const float4* u = (const float4*)supd;
        float a0=b_ih[tid],a1=0,a2=0,a3=0;
#pragma unroll
        for (int j = 0; j < 16; j++) {
            float4 a = u[j], c = w[j];
            a0 += a.x*c.x; a1 += a.y*c.y; a2 += a.z*c.z; a3 += a.w*c.w;
        }
        g_gi[(b*SS+s)*3*DD + tid] = (a0+a1)+(a2+a3);
    }
}

// ---------------------------------------------------------------------------
// k_upd2: GRU over slots (whh staged) -> MLP -> slots + next q'
// ---------------------------------------------------------------------------
__global__ __launch_bounds__(256)
void k_upd2(const float* __restrict__ w_hh, const float* __restrict__ b_hh,
            const float* __restrict__ w1, const float* __restrict__ b1,
            const float* __restrict__ w2, const float* __restrict__ b2,
            const float* __restrict__ lsg, const float* __restrict__ lsb,
            const float* __restrict__ lmg, const float* __restrict__ lmb,
            float* __restrict__ dout, int last) {
    extern __shared__ __align__(16) float sm[];
    float* whh = sm + V_WHH;     // [192][68]
    float* gis = sm + V_GI;      // [7][192]
    float* sl  = sm + V_SL;      // [7][64]
    float* xb  = sm + V_XB;
    float* hid = sm + V_HID;     // [7][128]
    float* h   = sm + V_H;
    float* ghs = sm + V_GH;      // [192]
    float* m7  = sm + V_M7;
    float* r7  = sm + V_R7;

    int b = blockIdx.x, tid = threadIdx.x;

    for (int i = tid; i < 3*DD*DD; i += 256) { int r = i>>6, e = i&63; whh[r*68+e] = w_hh[i]; }
    for (int i = tid; i < SS*3*DD; i += 256) gis[i] = g_gi[b*SS*3*DD + i];
    if (tid < DD) h[tid] = g_h0[b*DD+tid];
    __syncthreads();

    for (int s = 0; s < SS; s++) {
        if (tid < 3*DD) {
            const float4* w = (const float4*)(whh + tid*68);
            const float4* hv = (const float4*)h;
            float a0=b_hh[tid],a1=0,a2=0,a3=0;
#pragma unroll
            for (int j = 0; j < 16; j++) {
                float4 c = w[j], a = hv[j];
                a0 += a.x*c.x; a1 += a.y*c.y; a2 += a.z*c.z; a3 += a.w*c.w;
            }
            ghs[tid] = (a0+a1)+(a2+a3);
        }
        __syncthreads();
        if (tid < DD) {
            float r = 1.f/(1.f + __expf(-(gis[s*192+tid]     + ghs[tid])));
            float z = 1.f/(1.f + __expf(-(gis[s*192+64+tid]  + ghs[64+tid])));
            float nx = gis[s*192+128+tid] + r*ghs[128+tid];
            float n = 1.f - 2.f/(__expf(2.f*nx) + 1.f);   // tanh
            float hn = (1.f-z)*n + z*h[tid];
            h[tid] = hn;
            sl[s*DD+tid] = hn;
        }
        __syncthreads();
    }

    if (tid < SS) {
        float smv = 0.f, sq = 0.f;
        for (int d = 0; d < DD; d++) { float v = sl[tid*DD+d]; smv += v; sq += v*v; }
        float m = smv*(1.f/DD);
        m7[tid] = m; r7[tid] = rsqrtf(sq*(1.f/DD) - m*m + 1e-5f);
    }
    __syncthreads();
    for (int i = tid; i < SS*DD; i += 256) {
        int s = i >> 6, d = i & 63;
        xb[i] = (sl[i]-m7[s])*r7[s]*lmg[d] + lmb[d];
    }
    __syncthreads();
    for (int o = tid; o < SS*HH; o += 256) {
        int s = o >> 7, hc = o & 127;
        const float4* w = (const float4*)(w1 + hc*DD);
        const float4* u = (const float4*)(xb + s*DD);
        float a0=b1[hc],a1=0,a2=0,a3=0;
#pragma unroll
        for (int j = 0; j < 16; j++) {
            float4 a = u[j], c = w[j];
            a0 += a.x*c.x; a1 += a.y*c.y; a2 += a.z*c.z; a3 += a.w*c.w;
        }
        hid[o] = fmaxf((a0+a1)+(a2+a3), 0.f);
    }
    __syncthreads();
    for (int o = tid; o < SS*DD; o += 256) {
        int s = o >> 6, d = o & 63;
        const float4* w = (const float4*)(w2 + d*HH);
        const float4* u = (const float4*)(hid + s*HH);
        float a0=b2[d],a1=0,a2=0,a3=0;
#pragma unroll
        for (int j = 0; j < 32; j++) {
            float4 a = u[j], c = w[j];
            a0 += a.x*c.x; a1 += a.y*c.y; a2 += a.z*c.z; a3 += a.w*c.w;
        }
        float v = sl[o] + (a0+a1)+(a2+a3);
        sl[o] = v;
        g_slots[b*SS*DD+o] = v;
        dout[b*SS*DD+o] = v;
    }
    __syncthreads();

    if (!last) {
        if (tid < SS) {
            float smv = 0.f, sq = 0.f;
            for (int d = 0; d < DD; d++) { float v = sl[tid*DD+d]; smv += v; sq += v*v; }
            float m = smv*(1.f/DD);
            m7[tid] = m; r7[tid] = rsqrtf(sq*(1.f/DD) - m*m + 1e-5f);
        }
        __syncthreads();
        for (int i = tid; i < SS*DD; i += 256) {
            int s = i >> 6, d = i & 63;
            xb[i] = (sl[i]-m7[s])*r7[s]*lsg[d] + lsb[d];
        }
        __syncthreads();
        for (int o = tid; o < SS*DD; o += 256) {
            int s = o >> 6, d = o & 63;
            float a0=0,a1=0,a2=0,a3=0;
#pragma unroll
            for (int dp = 0; dp < DD; dp += 4) {
                a0 += xb[s*DD+dp+0]*g_P[(dp+0)*DD+d];
                a1 += xb[s*DD+dp+1]*g_P[(dp+1)*DD+d];
                a2 += xb[s*DD+dp+2]*g_P[(dp+2)*DD+d];
                a3 += xb[s*DD+dp+3]*g_P[(dp+3)*DD+d];
            }
            g_qp[b*SS*DD+o] = 0.125f*((a0+a1)+(a2+a3));
            g_U[b*SS*DD+o] = 0.f;
        }
        if (tid < SS) g_Z[b*SS+tid] = 0.f;
    }
}

// ---------------------------------------------------------------------------
extern "C" void kernel_launch(void* const* d_in, const int* in_sizes, int n_in,
                              void* d_out, int out_size) {
    const float* inputs     = (const float*)d_in[0];
    const float* ln_in_g    = (const float*)d_in[1];
    const float* ln_in_b    = (const float*)d_in[2];
    const float* ln_slots_g = (const float*)d_in[3];
    const float* ln_slots_b = (const float*)d_in[4];
    const float* ln_mlp_g   = (const float*)d_in[5];
    const float* ln_mlp_b   = (const float*)d_in[6];
    const float* Wq         = (const float*)d_in[7];
    const float* Wk         = (const float*)d_in[8];
    const float* Wv         = (const float*)d_in[9];
    const float* mu         = (const float*)d_in[10];
    const float* lsig       = (const float*)d_in[11];
    const float* w_ih       = (const float*)d_in[12];
    const float* w_hh       = (const float*)d_in[13];
    const float* b_ih       = (const float*)d_in[14];
    const float* b_hh       = (const float*)d_in[15];
    const float* w1         = (const float*)d_in[16];
    const float* b1         = (const float*)d_in[17];
    const float* w2         = (const float*)d_in[18];
    const float* b2         = (const float*)d_in[19];
    const float* nslots     = (const float*)d_in[20];
    const float* nh         = (const float*)d_in[21];
    float* out = (float*)d_out;

    cudaFuncSetAttribute(k_prep,  cudaFuncAttributeMaxDynamicSharedMemorySize, PREP_SMEM_BYTES);
    cudaFuncSetAttribute(k_attn,  cudaFuncAttributeMaxDynamicSharedMemorySize, ATTN_SMEM_BYTES);
    cudaFuncSetAttribute(k_upd2,  cudaFuncAttributeMaxDynamicSharedMemorySize, UPD2_SMEM_BYTES);

    k_setup<<<BB+1, 256>>>(mu, lsig, nslots, nh, Wq, Wk);
    k_prep<<<(BB*NN)/128, 256, PREP_SMEM_BYTES>>>(inputs, ln_in_g, ln_in_b);
    k_qp0<<<BB, 256>>>(ln_slots_g, ln_slots_b);
    for (int it = 0; it < 3; it++) {
        k_attn<<<BB*CHUNKS_PER_B, TPB, ATTN_SMEM_BYTES>>>();
        k_upd1<<<BB*SS, 192>>>(Wv, w_ih, b_ih);
        k_upd2<<<BB, 256, UPD2_SMEM_BYTES>>>(w_hh, b_hh, w1, b1, w2, b2,
                                             ln_slots_g, ln_slots_b, ln_mlp_g, ln_mlp_b,
                                             out, it == 2);
    }
}

// round 14
// speedup vs baseline: 2.1352x; 1.0090x over previous
#include <cuda_runtime.h>
#include <cuda_fp16.h>
#include <math.h>

#define BB 32
#define NN 16384
#define DD 64
#define SS 7
#define HH 128
#define TILE 128
#define NT 8                       // tiles per block
#define CHUNKS_PER_B 16            // 128 tiles / NT
#define TPB 256

__device__ __align__(16) float g_P[DD*DD];
__device__ __align__(16) float g_slots[BB*SS*DD];
__device__ __align__(16) float g_h0[BB*DD];
__device__ __align__(16) float g_qp[BB*SS*DD];
__device__ __align__(16) float g_U[BB*SS*DD];
__device__ float g_Z[BB*SS];
__device__ __align__(16) float g_Sx[BB*DD];             // sum_n xn (for eps fold)
__device__ __align__(16) float g_gi[BB*SS*3*DD];        // GRU input gates
__device__ __align__(16) __half g_xn[(long)BB*NN*DD];   // 64 MB LN(x) cache

// ---- k_attn smem layout (bytes): 2 x 128-row buffers ----
#define A_XN0   0        // 128 rows * 72 halves = 18432 B
#define A_XN1   18432
#define A_QPH   36864    // 8 * 72 halves = 1152 B
#define A_PT    38016    // 8 * 136 halves = 2176 B
#define A_PART  40192    // 2 * 64 * 8 fp32 = 4096 B
#define ATTN_SMEM_BYTES 44288

// ---- k_prep_attn0 smem layout (bytes) ----
#define F_IN    0        // fp32 [128][17] float4 = 34816 B
#define F_XN    34816    // fp16 [128][9] uint4 = 18432 B
#define F_QPH   53248    // 1152 B
#define F_PT    54400    // 2176 B
#define F_PART  56576    // 4096 B
#define F_G     60672    // 256 B
#define F_B     60928    // 256 B
#define FUSED_SMEM_BYTES 61184

// ---- k_upd2 smem layout (floats) ----
#define V_WHH 0           // 192*68 = 13056
#define V_GI  13056       // 1344
#define V_SL  14400       // 448
#define V_XB  14848       // 448
#define V_HID 15296       // 896
#define V_H   16192       // 64
#define V_GH  16256       // 192
#define V_M7  16448       // 8
#define V_R7  16456       // 8
#define UPD2_SMEM_BYTES ((16464)*4)

__device__ __forceinline__ unsigned pack_h2(float a, float b) {
    __half2 h = __float22half2_rn(make_float2(a, b));
    return *(unsigned*)&h;
}

#define LDSM_X4(a0,a1,a2,a3,addr) \
    asm volatile("ldmatrix.sync.aligned.m8n8.x4.shared.b16 {%0,%1,%2,%3}, [%4];" \
        : "=r"(a0),"=r"(a1),"=r"(a2),"=r"(a3) : "r"(addr))
#define LDSM_X4_T(a0,a1,a2,a3,addr) \
    asm volatile("ldmatrix.sync.aligned.m8n8.x4.trans.shared.b16 {%0,%1,%2,%3}, [%4];" \
        : "=r"(a0),"=r"(a1),"=r"(a2),"=r"(a3) : "r"(addr))
#define MMA16816(c0,c1,c2,c3,a0,a1,a2,a3,b0,b1) \
    asm volatile("mma.sync.aligned.m16n8k16.row.col.f32.f16.f16.f32 " \
        "{%0,%1,%2,%3}, {%4,%5,%6,%7}, {%8,%9}, {%0,%1,%2,%3};" \
        : "+f"(c0),"+f"(c1),"+f"(c2),"+f"(c3) \
        : "r"(a0),"r"(a1),"r"(a2),"r"(a3),"r"(b0),"r"(b1))
#define CP_ASYNC16(dst, src) \
    asm volatile("cp.async.cg.shared.global [%0], [%1], 16;" :: "r"(dst), "l"(src))
#define CP_COMMIT() asm volatile("cp.async.commit_group;" ::: "memory")
#define CP_WAIT(n)  asm volatile("cp.async.wait_group %0;" :: "n"(n) : "memory")

// ---------------------------------------------------------------------------
// k_setup: blocks 0..31 -> slots/h0 init + zero U,Z,Sx.  block 32 -> P=Wq^T Wk
// ---------------------------------------------------------------------------
__global__ void k_setup(const float* __restrict__ mu, const float* __restrict__ lsig,
                        const float* __restrict__ nslots, const float* __restrict__ nh,
                        const float* __restrict__ Wq, const float* __restrict__ Wk) {
    int blk = blockIdx.x, tid = threadIdx.x;
    if (blk < BB) {
        int b = blk;
        for (int i = tid; i < SS*DD; i += blockDim.x) {
            int d = i & (DD-1);
            float sg = __expf(lsig[d]);
            g_slots[b*SS*DD + i] = mu[d] + sg * nslots[b*SS*DD + i];
            g_U[b*SS*DD + i] = 0.f;
        }
        for (int d = tid; d < DD; d += blockDim.x) {
            float sg = __expf(lsig[d]);
            g_h0[b*DD + d] = mu[d] + sg * nh[b*DD + d];
            g_Sx[b*DD + d] = 0.f;
        }
        if (tid < SS) g_Z[b*SS + tid] = 0.f;
    } else {
        __shared__ float sq[DD*DD], sk[DD*DD];
        for (int i = tid; i < DD*DD; i += blockDim.x) { sq[i] = Wq[i]; sk[i] = Wk[i]; }
        __syncthreads();
        for (int i = tid; i < DD*DD; i += blockDim.x) {
            int dp = i >> 6, d = i & 63;
            float acc = 0.f;
            for (int e = 0; e < DD; e++) acc += sq[e*DD+dp] * sk[e*DD+d];
            g_P[i] = acc;
        }
    }
}

// ---------------------------------------------------------------------------
// k_qp0: q'[b,s,:] = scale * LN_slots(slots[b,s]) @ P
// ---------------------------------------------------------------------------
__global__ void k_qp0(const float* __restrict__ lsg, const float* __restrict__ lsb) {
    int b = blockIdx.x, tid = threadIdx.x;
    __shared__ float sl[SS*DD], sn[SS*DD], m7[SS], r7[SS];
    for (int i = tid; i < SS*DD; i += blockDim.x) sl[i] = g_slots[b*SS*DD+i];
    __syncthreads();
    if (tid < SS) {
        float sm = 0.f, sq = 0.f;
        for (int d = 0; d < DD; d++) { float v = sl[tid*DD+d]; sm += v; sq += v*v; }
        float m = sm * (1.f/DD);
        m7[tid] = m;
        r7[tid] = rsqrtf(sq*(1.f/DD) - m*m + 1e-5f);
    }
    __syncthreads();
    for (int i = tid; i < SS*DD; i += blockDim.x) {
        int s = i >> 6, d = i & 63;
        sn[i] = (sl[i]-m7[s])*r7[s]*lsg[d] + lsb[d];
    }
    __syncthreads();
    for (int o = tid; o < SS*DD; o += blockDim.x) {
        int s = o >> 6, d = o & 63;
        float acc = 0.f;
        for (int dp = 0; dp < DD; dp++) acc += sn[s*DD+dp] * g_P[dp*DD+d];
        g_qp[b*SS*DD+o] = 0.125f * acc;
    }
}

// ---------------------------------------------------------------------------
// k_prep_attn0: fused LN(inputs)->g_xn + iteration-0 attention.
// Persistent 8-tile blocks; U/Z/Sx accumulate in registers; one epilogue.
// ---------------------------------------------------------------------------
__global__ __launch_bounds__(TPB)
void k_prep_attn0(const float* __restrict__ x_in,
                  const float* __restrict__ lg, const float* __restrict__ lb) {
    extern __shared__ __align__(16) char smem[];
    float4* s_in  = (float4*)(smem + F_IN);      // [128][17]
    uint4*  s_xn4 = (uint4*)(smem + F_XN);       // [128][9]
    __half* s_xnh = (__half*)(smem + F_XN);      // pitch 72 halves
    __half* qph   = (__half*)(smem + F_QPH);     // [8][72]
    __half* pT    = (__half*)(smem + F_PT);      // [8][136]
    float*  part  = (float*)(smem + F_PART);     // [2][64][8]
    float*  s_g   = (float*)(smem + F_G);
    float*  s_b   = (float*)(smem + F_B);

    int b     = blockIdx.x >> 4;                 // CHUNKS_PER_B = 16
    int chunk = blockIdx.x & (CHUNKS_PER_B-1);
    int tid = threadIdx.x;
    int w   = tid >> 5, l = tid & 31;

    long row0 = (long)b*NN + (long)chunk*NT*TILE;
    unsigned in_sa = (unsigned)__cvta_generic_to_shared(smem + F_IN);
    unsigned xn_sa = (unsigned)__cvta_generic_to_shared(smem + F_XN);

    if (tid < DD) { s_g[tid] = lg[tid]; s_b[tid] = lb[tid]; }
    // stage q' -> fp16
    {
        int n = tid >> 5, kp = tid & 31;
        float2 v = (n < 7) ? ((const float2*)(g_qp + b*SS*DD + n*DD))[kp]
                           : make_float2(0.f, 0.f);
        *(unsigned*)(qph + n*72 + kp*2) = pack_h2(v.x, v.y);
    }

    int e   = 2*(l & 3);
    int gid = l >> 2;
    bool lastc = (l & 3) == 3;

    // persistent accumulators
    float zacc0 = 0.f, zacc1 = 0.f;
    float u0 = 0.f, u1 = 0.f, u2 = 0.f, u3 = 0.f;
    float sx = 0.f;                              // tid<64 column sum

    // phase-1 addressing
    int arow = (l & 15);
    int acol = (l >> 4) << 3;
    int r0p1 = w*16;
    // phase-2 addressing
    int mt = w & 3, kh = w >> 2;
    int d0 = mt*16;
    int Rr = kh*64;
    int trow = (l & 7) + ((l >> 4) << 3);
    int tcol = ((l >> 3) & 1) << 3;

    for (int i = 0; i < NT; i++) {
        // ---- load fp32 tile (2048 x 16B) ----
        {
            const float4* gin = (const float4*)x_in + (row0 + (long)i*TILE)*16;
#pragma unroll
            for (int jj = 0; jj < 8; jj++) {
                int li = jj*256 + tid;
                unsigned dst = in_sa + (unsigned)(((li>>4)*17 + (li&15))*16);
                CP_ASYNC16(dst, gin + li);
            }
            CP_COMMIT(); CP_WAIT(0);
        }
        __syncthreads();

        // ---- LN by 128 threads -> fp16 tile ----
        if (tid < 128) {
            const float4* xr = s_in + tid*17;
            float4 x[16];
#pragma unroll
            for (int j = 0; j < 16; j++) x[j] = xr[j];
            float sm = 0.f, sq = 0.f;
#pragma unroll
            for (int j = 0; j < 16; j++) {
                sm += x[j].x + x[j].y + x[j].z + x[j].w;
                sq += x[j].x*x[j].x + x[j].y*x[j].y + x[j].z*x[j].z + x[j].w*x[j].w;
            }
            float m = sm * (1.f/DD);
            float rstd = rsqrtf(sq*(1.f/DD) - m*m + 1e-5f);
#pragma unroll
            for (int j = 0; j < 8; j++) {
                float4 a = x[2*j], c = x[2*j+1];
                float n0 = (a.x-m)*rstd*s_g[8*j+0] + s_b[8*j+0];
                float n1 = (a.y-m)*rstd*s_g[8*j+1] + s_b[8*j+1];
                float n2 = (a.z-m)*rstd*s_g[8*j+2] + s_b[8*j+2];
                float n3 = (a.w-m)*rstd*s_g[8*j+3] + s_b[8*j+3];
                float n4 = (c.x-m)*rstd*s_g[8*j+4] + s_b[8*j+4];
                float n5 = (c.y-m)*rstd*s_g[8*j+5] + s_b[8*j+5];
                float n6 = (c.z-m)*rstd*s_g[8*j+6] + s_b[8*j+6];
                float n7 = (c.w-m)*rstd*s_g[8*j+7] + s_b[8*j+7];
                uint4 o;
                o.x = pack_h2(n0, n1);
                o.y = pack_h2(n2, n3);
                o.z = pack_h2(n4, n5);
                o.w = pack_h2(n6, n7);
                s_xn4[tid*9 + j] = o;
            }
        }
        __syncthreads();

        // ---- write fp16 tile to gmem (coalesced) ----
        {
            uint4* gout = (uint4*)g_xn + (row0 + (long)i*TILE)*8;
#pragma unroll
            for (int jj = 0; jj < 4; jj++) {
                int li = jj*256 + tid;
                gout[li] = s_xn4[(li>>3)*9 + (li&7)];
            }
        }
        // ---- Sx partial (tid<64, fp16-consistent) ----
        if (tid < DD) {
            float acc = 0.f;
            for (int r = 0; r < TILE; r++) acc += __half2float(s_xnh[r*72 + tid]);
            sx += acc;
        }

        // ---- phase 1: GEMM1 + softmax -> pT ----
        {
            float c0=0.f,c1=0.f,c2=0.f,c3=0.f;
#pragma unroll
            for (int kk = 0; kk < 4; kk++) {
                unsigned addr = xn_sa + (unsigned)(((r0p1 + arow)*72 + kk*16 + acol)*2);
                unsigned a0,a1,a2,a3;
                LDSM_X4(a0,a1,a2,a3, addr);
                unsigned b0 = *(const unsigned*)(qph + gid*72 + kk*16 + e);
                unsigned b1 = *(const unsigned*)(qph + gid*72 + kk*16 + e + 8);
                MMA16816(c0,c1,c2,c3, a0,a1,a2,a3, b0,b1);
            }
            int rA = r0p1 + gid, rB = rA + 8;
            float v1 = lastc ? -1e30f : c1;
            float v3 = lastc ? -1e30f : c3;
            float m0 = fmaxf(c0, v1), m1 = fmaxf(c2, v3);
            m0 = fmaxf(m0, __shfl_xor_sync(0xffffffffu, m0, 1));
            m0 = fmaxf(m0, __shfl_xor_sync(0xffffffffu, m0, 2));
            m1 = fmaxf(m1, __shfl_xor_sync(0xffffffffu, m1, 1));
            m1 = fmaxf(m1, __shfl_xor_sync(0xffffffffu, m1, 2));
            float e0 = __expf(c0 - m0), e1 = lastc ? 0.f : __expf(c1 - m0);
            float e2 = __expf(c2 - m1), e3 = lastc ? 0.f : __expf(c3 - m1);
            float s0 = e0 + e1, s1 = e2 + e3;
            s0 += __shfl_xor_sync(0xffffffffu, s0, 1);
            s0 += __shfl_xor_sync(0xffffffffu, s0, 2);
            s1 += __shfl_xor_sync(0xffffffffu, s1, 1);
            s1 += __shfl_xor_sync(0xffffffffu, s1, 2);
            float p0 = e0/s0, p1 = e1/s0, p2 = e2/s1, p3 = e3/s1;
            pT[e*136 + rA]     = __float2half_rn(p0);
            pT[(e+1)*136 + rA] = __float2half_rn(p1);
            pT[e*136 + rB]     = __float2half_rn(p2);
            pT[(e+1)*136 + rB] = __float2half_rn(p3);
            zacc0 += p0 + p2; zacc1 += p1 + p3;
        }
        __syncthreads();

        // ---- phase 2: GEMM2 accumulate into persistent C-regs ----
#pragma unroll
        for (int kk = 0; kk < 4; kk++) {
            int k0 = Rr + kk*16;
            unsigned addr = xn_sa + (unsigned)(((k0 + trow)*72 + d0 + tcol)*2);
            unsigned a0,a1,a2,a3;
            LDSM_X4_T(a0,a1,a2,a3, addr);
            unsigned b0 = *(const unsigned*)(pT + gid*136 + k0 + e);
            unsigned b1 = *(const unsigned*)(pT + gid*136 + k0 + e + 8);
            MMA16816(u0,u1,u2,u3, a0,a1,a2,a3, b0,b1);
        }
        __syncthreads();   // tile fully consumed before reuse
    }

    // ---- epilogue: Sx + Z atomics ----
    if (tid < DD) atomicAdd(&g_Sx[b*DD + tid], sx);
    zacc0 += __shfl_xor_sync(0xffffffffu, zacc0, 4);
    zacc0 += __shfl_xor_sync(0xffffffffu, zacc0, 8);
    zacc0 += __shfl_xor_sync(0xffffffffu, zacc0, 16);
    zacc1 += __shfl_xor_sync(0xffffffffu, zacc1, 4);
    zacc1 += __shfl_xor_sync(0xffffffffu, zacc1, 8);
    zacc1 += __shfl_xor_sync(0xffffffffu, zacc1, 16);
    if (l < 4) {
        atomicAdd(&g_Z[b*SS + 2*l], zacc0);
        if (l < 3) atomicAdd(&g_Z[b*SS + 2*l + 1], zacc1);
    }

    // ---- epilogue: U partial store, merge, REDs ----
    {
        int dim = d0 + gid;
        float2* pp = (float2*)part;
        pp[kh*256 + dim*4 + (e>>1)]     = make_float2(u0, u1);
        pp[kh*256 + (dim+8)*4 + (e>>1)] = make_float2(u2, u3);
    }
    __syncthreads();
#pragma unroll
    for (int i = tid; i < 512; i += TPB) {
        int s = i & 7;
        if (s < 7) {
            int dim = i >> 3;
            float v = part[i] + part[512 + i];
            atomicAdd(&g_U[(b*SS + s)*DD + dim], v);
        }
    }
}

// ---------------------------------------------------------------------------
// k_attn: persistent 8-tile blocks (iterations 1,2) — round-13 version
// ---------------------------------------------------------------------------
__global__ __launch_bounds__(TPB)
void k_attn() {
    extern __shared__ __align__(16) char smem[];
    __half* qph  = (__half*)(smem + A_QPH);     // [8][72]
    __half* pT   = (__half*)(smem + A_PT);      // [8][136]
    float*  part = (float*)(smem + A_PART);     // [2][64][8]

    int b     = blockIdx.x >> 4;                // CHUNKS_PER_B = 16
    int chunk = blockIdx.x & (CHUNKS_PER_B-1);
    int tid = threadIdx.x;
    int w   = tid >> 5, l = tid & 31;

    unsigned sbuf0 = (unsigned)__cvta_generic_to_shared(smem + A_XN0);
    unsigned sbuf1 = (unsigned)__cvta_generic_to_shared(smem + A_XN1);
    const uint4* gx = (const uint4*)g_xn + ((long)b*NN + (long)chunk*NT*TILE)*8;

#define ISSUE_TILE(i) do { \
        unsigned dstb = ((i) & 1) ? sbuf1 : sbuf0; \
        const uint4* src = gx + (long)(i)*TILE*8; \
        _Pragma("unroll") \
        for (int jj = 0; jj < 4; jj++) { \
            int li = jj*256 + tid; \
            unsigned dst = dstb + (unsigned)(((li>>3)*9 + (li&7))*16); \
            CP_ASYNC16(dst, src + li); \
        } \
        CP_COMMIT(); \
    } while (0)

    ISSUE_TILE(0);
    ISSUE_TILE(1);

    {
        int n = tid >> 5, kp = tid & 31;
        float2 v = (n < 7) ? ((const float2*)(g_qp + b*SS*DD + n*DD))[kp]
                           : make_float2(0.f, 0.f);
        *(unsigned*)(qph + n*72 + kp*2) = pack_h2(v.x, v.y);
    }

    int e   = 2*(l & 3);
    int gid = l >> 2;
    bool lastc = (l & 3) == 3;

    float zacc0 = 0.f, zacc1 = 0.f;
    float u0 = 0.f, u1 = 0.f, u2 = 0.f, u3 = 0.f;

    int arow = (l & 15);
    int acol = (l >> 4) << 3;
    int r0p1 = w*16;
    int mt = w & 3, kh = w >> 2;
    int d0 = mt*16;
    int Rr = kh*64;
    int trow = (l & 7) + ((l >> 4) << 3);
    int tcol = ((l >> 3) & 1) << 3;

    for (int i = 0; i < NT; i++) {
        if (i == NT-1) { CP_WAIT(0); } else { CP_WAIT(1); }
        __syncthreads();
        unsigned xn_sa = (i & 1) ? sbuf1 : sbuf0;

        {
            float c0=0.f,c1=0.f,c2=0.f,c3=0.f;
#pragma unroll
            for (int kk = 0; kk < 4; kk++) {
                unsigned addr = xn_sa + (unsigned)(((r0p1 + arow)*72 + kk*16 + acol)*2);
                unsigned a0,a1,a2,a3;
                LDSM_X4(a0,a1,a2,a3, addr);
                unsigned b0 = *(const unsigned*)(qph + gid*72 + kk*16 + e);
                unsigned b1 = *(const unsigned*)(qph + gid*72 + kk*16 + e + 8);
                MMA16816(c0,c1,c2,c3, a0,a1,a2,a3, b0,b1);
            }
            int rA = r0p1 + gid, rB = rA + 8;
            float v1 = lastc ? -1e30f : c1;
            float v3 = lastc ? -1e30f : c3;
            float m0 = fmaxf(c0, v1), m1 = fmaxf(c2, v3);
            m0 = fmaxf(m0, __shfl_xor_sync(0xffffffffu, m0, 1));
            m0 = fmaxf(m0, __shfl_xor_sync(0xffffffffu, m0, 2));
            m1 = fmaxf(m1, __shfl_xor_sync(0xffffffffu, m1, 1));
            m1 = fmaxf(m1, __shfl_xor_sync(0xffffffffu, m1, 2));
            float e0 = __expf(c0 - m0), e1 = lastc ? 0.f : __expf(c1 - m0);
            float e2 = __expf(c2 - m1), e3 = lastc ? 0.f : __expf(c3 - m1);
            float s0 = e0 + e1, s1 = e2 + e3;
            s0 += __shfl_xor_sync(0xffffffffu, s0, 1);
            s0 += __shfl_xor_sync(0xffffffffu, s0, 2);
            s1 += __shfl_xor_sync(0xffffffffu, s1, 1);
            s1 += __shfl_xor_sync(0xffffffffu, s1, 2);
            float p0 = e0/s0, p1 = e1/s0, p2 = e2/s1, p3 = e3/s1;
            pT[e*136 + rA]     = __float2half_rn(p0);
            pT[(e+1)*136 + rA] = __float2half_rn(p1);
            pT[e*136 + rB]     = __float2half_rn(p2);
            pT[(e+1)*136 + rB] = __float2half_rn(p3);
            zacc0 += p0 + p2; zacc1 += p1 + p3;
        }
        __syncthreads();

#pragma unroll
        for (int kk = 0; kk < 4; kk++) {
            int k0 = Rr + kk*16;
            unsigned addr = xn_sa + (unsigned)(((k0 + trow)*72 + d0 + tcol)*2);
            unsigned a0,a1,a2,a3;
            LDSM_X4_T(a0,a1,a2,a3, addr);
            unsigned b0 = *(const unsigned*)(pT + gid*136 + k0 + e);
            unsigned b1 = *(const unsigned*)(pT + gid*136 + k0 + e + 8);
            MMA16816(u0,u1,u2,u3, a0,a1,a2,a3, b0,b1);
        }
        __syncthreads();

        if (i + 2 < NT) ISSUE_TILE(i + 2);
    }

    zacc0 += __shfl_xor_sync(0xffffffffu, zacc0, 4);
    zacc0 += __shfl_xor_sync(0xffffffffu, zacc0, 8);
    zacc0 += __shfl_xor_sync(0xffffffffu, zacc0, 16);
    zacc1 += __shfl_xor_sync(0xffffffffu, zacc1, 4);
    zacc1 += __shfl_xor_sync(0xffffffffu, zacc1, 8);
    zacc1 += __shfl_xor_sync(0xffffffffu, zacc1, 16);
    if (l < 4) {
        atomicAdd(&g_Z[b*SS + 2*l], zacc0);
        if (l < 3) atomicAdd(&g_Z[b*SS + 2*l + 1], zacc1);
    }

    {
        int dim = d0 + gid;
        float2* pp = (float2*)part;
        pp[kh*256 + dim*4 + (e>>1)]     = make_float2(u0, u1);
        pp[kh*256 + (dim+8)*4 + (e>>1)] = make_float2(u2, u3);
    }
    __syncthreads();
#pragma unroll
    for (int i = tid; i < 512; i += TPB) {
        int s = i & 7;
        if (s < 7) {
            int dim = i >> 3;
            float v = part[i] + part[512 + i];
            atomicAdd(&g_U[(b*SS + s)*DD + dim], v);
        }
    }
#undef ISSUE_TILE
}

// ---------------------------------------------------------------------------
// k_upd1: per (b,s): updates = ((U + eps*Sx) . Wv^T)/(Z + N*eps), gi = ...
// ---------------------------------------------------------------------------
__global__ __launch_bounds__(192)
void k_upd1(const float* __restrict__ Wv,
            const float* __restrict__ w_ih, const float* __restrict__ b_ih) {
    int blk = blockIdx.x;           // 0..223
    int b = blk / SS, s = blk - b*SS;
    int tid = threadIdx.x;
    __shared__ float sU[DD], supd[DD];
    __shared__ float sZ;

    if (tid < DD) sU[tid] = g_U[(b*SS+s)*DD + tid] + 1e-8f * g_Sx[b*DD + tid];
    if (tid == 0) sZ = g_Z[b*SS+s] + 1.6384e-4f;   // + N*eps
    __syncthreads();

    if (tid < DD) {
        const float4* w = (const float4*)(Wv + tid*DD);
        const float4* u = (const float4*)sU;
        float a0=0,a1=0,a2=0,a3=0;
#pragma unroll
        for (int j = 0; j < 16; j++) {
            float4 a = u[j], c = w[j];
            a0 += a.x*c.x; a1 += a.y*c.y; a2 += a.z*c.z; a3 += a.w*c.w;
        }
        supd[tid] = ((a0+a1)+(a2+a3)) / sZ;
    }
    __syncthreads();

    {
        const float4* w = (const float4*)(w_ih + tid*DD);
        const float4* u = (const float4*)supd;
        float a0=b_ih[tid],a1=0,a2=0,a3=0;
#pragma unroll
        for (int j = 0; j < 16; j++) {
            float4 a = u[j], c = w[j];
            a0 += a.x*c.x; a1 += a.y*c.y; a2 += a.z*c.z; a3 += a.w*c.w;
        }
        g_gi[(b*SS+s)*3*DD + tid] = (a0+a1)+(a2+a3);
    }
}

// ---------------------------------------------------------------------------
// k_upd2: GRU over slots (whh staged) -> MLP -> slots + next q'
// ---------------------------------------------------------------------------
__global__ __launch_bounds__(256)
void k_upd2(const float* __restrict__ w_hh, const float* __restrict__ b_hh,
            const float* __restrict__ w1, const float* __restrict__ b1,
            const float* __restrict__ w2, const float* __restrict__ b2,
            const float* __restrict__ lsg, const float* __restrict__ lsb,
            const float* __restrict__ lmg, const float* __restrict__ lmb,
            float* __restrict__ dout, int last) {
    extern __shared__ __align__(16) float sm[];
    float* whh = sm + V_WHH;     // [192][68]
    float* gis = sm + V_GI;      // [7][192]
    float* sl  = sm + V_SL;      // [7][64]
    float* xb  = sm + V_XB;
    float* hid = sm + V_HID;     // [7][128]
    float* h   = sm + V_H;
    float* ghs = sm + V_GH;      // [192]
    float* m7  = sm + V_M7;
    float* r7  = sm + V_R7;

    int b = blockIdx.x, tid = threadIdx.x;

    for (int i = tid; i < 3*DD*DD; i += 256) { int r = i>>6, e = i&63; whh[r*68+e] = w_hh[i]; }
    for (int i = tid; i < SS*3*DD; i += 256) gis[i] = g_gi[b*SS*3*DD + i];
    if (tid < DD) h[tid] = g_h0[b*DD+tid];
    __syncthreads();

    for (int s = 0; s < SS; s++) {
        if (tid < 3*DD) {
            const float4* w = (const float4*)(whh + tid*68);
            const float4* hv = (const float4*)h;
            float a0=b_hh[tid],a1=0,a2=0,a3=0;
#pragma unroll
            for (int j = 0; j < 16; j++) {
                float4 c = w[j], a = hv[j];
                a0 += a.x*c.x; a1 += a.y*c.y; a2 += a.z*c.z; a3 += a.w*c.w;
            }
            ghs[tid] = (a0+a1)+(a2+a3);
        }
        __syncthreads();
        if (tid < DD) {
            float r = 1.f/(1.f + __expf(-(gis[s*192+tid]     + ghs[tid])));
            float z = 1.f/(1.f + __expf(-(gis[s*192+64+tid]  + ghs[64+tid])));
            float nx = gis[s*192+128+tid] + r*ghs[128+tid];
            float n = 1.f - 2.f/(__expf(2.f*nx) + 1.f);   // tanh
            float hn = (1.f-z)*n + z*h[tid];
            h[tid] = hn;
            sl[s*DD+tid] = hn;
        }
        __syncthreads();
    }

    if (tid < SS) {
        float smv = 0.f, sq = 0.f;
        for (int d = 0; d < DD; d++) { float v = sl[tid*DD+d]; smv += v; sq += v*v; }
        float m = smv*(1.f/DD);
        m7[tid] = m; r7[tid] = rsqrtf(sq*(1.f/DD) - m*m + 1e-5f);
    }
    __syncthreads();
    for (int i = tid; i < SS*DD; i += 256) {
        int s = i >> 6, d = i & 63;
        xb[i] = (sl[i]-m7[s])*r7[s]*lmg[d] + lmb[d];
    }
    __syncthreads();
    for (int o = tid; o < SS*HH; o += 256) {
        int s = o >> 7, hc = o & 127;
        const float4* w = (const float4*)(w1 + hc*DD);
        const float4* u = (const float4*)(xb + s*DD);
        float a0=b1[hc],a1=0,a2=0,a3=0;
#pragma unroll
        for (int j = 0; j < 16; j++) {
            float4 a = u[j], c = w[j];
            a0 += a.x*c.x; a1 += a.y*c.y; a2 += a.z*c.z; a3 += a.w*c.w;
        }
        hid[o] = fmaxf((a0+a1)+(a2+a3), 0.f);
    }
    __syncthreads();
    for (int o = tid; o < SS*DD; o += 256) {
        int s = o >> 6, d = o & 63;
        const float4* w = (const float4*)(w2 + d*HH);
        const float4* u = (const float4*)(hid + s*HH);
        float a0=b2[d],a1=0,a2=0,a3=0;
#pragma unroll
        for (int j = 0; j < 32; j++) {
            float4 a = u[j], c = w[j];
            a0 += a.x*c.x; a1 += a.y*c.y; a2 += a.z*c.z; a3 += a.w*c.w;
        }
        float v = sl[o] + (a0+a1)+(a2+a3);
        sl[o] = v;
        g_slots[b*SS*DD+o] = v;
        dout[b*SS*DD+o] = v;
    }
    __syncthreads();

    if (!last) {
        if (tid < SS) {
            float smv = 0.f, sq = 0.f;
            for (int d = 0; d < DD; d++) { float v = sl[tid*DD+d]; smv += v; sq += v*v; }
            float m = smv*(1.f/DD);
            m7[tid] = m; r7[tid] = rsqrtf(sq*(1.f/DD) - m*m + 1e-5f);
        }
        __syncthreads();
        for (int i = tid; i < SS*DD; i += 256) {
            int s = i >> 6, d = i & 63;
            xb[i] = (sl[i]-m7[s])*r7[s]*lsg[d] + lsb[d];
        }
        __syncthreads();
        for (int o = tid; o < SS*DD; o += 256) {
            int s = o >> 6, d = o & 63;
            float a0=0,a1=0,a2=0,a3=0;
#pragma unroll
            for (int dp = 0; dp < DD; dp += 4) {
                a0 += xb[s*DD+dp+0]*g_P[(dp+0)*DD+d];
                a1 += xb[s*DD+dp+1]*g_P[(dp+1)*DD+d];
                a2 += xb[s*DD+dp+2]*g_P[(dp+2)*DD+d];
                a3 += xb[s*DD+dp+3]*g_P[(dp+3)*DD+d];
            }
            g_qp[b*SS*DD+o] = 0.125f*((a0+a1)+(a2+a3));
            g_U[b*SS*DD+o] = 0.f;
        }
        if (tid < SS) g_Z[b*SS+tid] = 0.f;
    }
}

// ---------------------------------------------------------------------------
extern "C" void kernel_launch(void* const* d_in, const int* in_sizes, int n_in,
                              void* d_out, int out_size) {
    const float* inputs     = (const float*)d_in[0];
    const float* ln_in_g    = (const float*)d_in[1];
    const float* ln_in_b    = (const float*)d_in[2];
    const float* ln_slots_g = (const float*)d_in[3];
    const float* ln_slots_b = (const float*)d_in[4];
    const float* ln_mlp_g   = (const float*)d_in[5];
    const float* ln_mlp_b   = (const float*)d_in[6];
    const float* Wq         = (const float*)d_in[7];
    const float* Wk         = (const float*)d_in[8];
    const float* Wv         = (const float*)d_in[9];
    const float* mu         = (const float*)d_in[10];
    const float* lsig       = (const float*)d_in[11];
    const float* w_ih       = (const float*)d_in[12];
    const float* w_hh       = (const float*)d_in[13];
    const float* b_ih       = (const float*)d_in[14];
    const float* b_hh       = (const float*)d_in[15];
    const float* w1         = (const float*)d_in[16];
    const float* b1         = (const float*)d_in[17];
    const float* w2         = (const float*)d_in[18];
    const float* b2         = (const float*)d_in[19];
    const float* nslots     = (const float*)d_in[20];
    const float* nh         = (const float*)d_in[21];
    float* out = (float*)d_out;

    cudaFuncSetAttribute(k_prep_attn0, cudaFuncAttributeMaxDynamicSharedMemorySize, FUSED_SMEM_BYTES);
    cudaFuncSetAttribute(k_attn,  cudaFuncAttributeMaxDynamicSharedMemorySize, ATTN_SMEM_BYTES);
    cudaFuncSetAttribute(k_upd2,  cudaFuncAttributeMaxDynamicSharedMemorySize, UPD2_SMEM_BYTES);

    k_setup<<<BB+1, 256>>>(mu, lsig, nslots, nh, Wq, Wk);
    k_qp0<<<BB, 256>>>(ln_slots_g, ln_slots_b);
    k_prep_attn0<<<BB*CHUNKS_PER_B, TPB, FUSED_SMEM_BYTES>>>(inputs, ln_in_g, ln_in_b);
    for (int it = 0; it < 3; it++) {
        if (it > 0) k_attn<<<BB*CHUNKS_PER_B, TPB, ATTN_SMEM_BYTES>>>();
        k_upd1<<<BB*SS, 192>>>(Wv, w_ih, b_ih);
        k_upd2<<<BB, 256, UPD2_SMEM_BYTES>>>(w_hh, b_hh, w1, b1, w2, b2,
                                             ln_slots_g, ln_slots_b, ln_mlp_g, ln_mlp_b,
                                             out, it == 2);
    }
}

// round 16
// speedup vs baseline: 2.2151x; 1.0374x over previous
#include <cuda_runtime.h>
#include <cuda_fp16.h>
#include <math.h>

#define BB 32
#define NN 16384
#define DD 64
#define SS 7
#define HH 128
#define TILE 128
#define NT 8                       // tiles per block
#define CHUNKS_PER_B 16            // 128 tiles / NT
#define TPB 256

__device__ __align__(16) float g_P[DD*DD];
__device__ __align__(16) float g_slots[BB*SS*DD];
__device__ __align__(16) float g_h0[BB*DD];
__device__ __align__(16) float g_qp[BB*SS*DD];
__device__ __align__(16) float g_U[BB*SS*DD];
__device__ float g_Z[BB*SS];
__device__ __align__(16) float g_Sx[BB*DD];             // sum_n xn (for eps fold)
__device__ __align__(16) float g_gi[BB*SS*3*DD];        // GRU input gates
__device__ __align__(16) __half g_xn[(long)BB*NN*DD];   // 64 MB LN(x) cache

// ---- k_attn smem layout (bytes): 2 x 128-row buffers ----
#define A_XN0   0        // 128 rows * 72 halves = 18432 B
#define A_XN1   18432
#define A_QPH   36864    // 8 * 72 halves = 1152 B
#define A_PT    38016    // 8 * 136 halves = 2176 B
#define A_PART  40192    // 2 * 64 * 8 fp32 = 4096 B
#define ATTN_SMEM_BYTES 44288

// ---- k_prep_attn0 smem layout (bytes), double-buffered fp32 input ----
#define F_IN0   0        // fp32 [128][17] float4 = 34816 B
#define F_IN1   34816
#define F_XN    69632    // fp16 [128][9] uint4 = 18432 B
#define F_QPH   88064    // 1152 B
#define F_PT    89216    // 2176 B
#define F_PART  91392    // 4096 B
#define F_G     95488    // 256 B
#define F_B     95744    // 256 B
#define FUSED_SMEM_BYTES 96000

// ---- k_upd2 smem layout (floats) ----
#define V_WHH 0           // 192*68 = 13056
#define V_GI  13056       // 1344
#define V_SL  14400       // 448
#define V_XB  14848       // 448
#define V_HID 15296       // 896
#define V_H   16192       // 64
#define V_GH  16256       // 192
#define V_M7  16448       // 8
#define V_R7  16456       // 8
#define UPD2_SMEM_BYTES ((16464)*4)

__device__ __forceinline__ unsigned pack_h2(float a, float b) {
    __half2 h = __float22half2_rn(make_float2(a, b));
    return *(unsigned*)&h;
}

#define LDSM_X4(a0,a1,a2,a3,addr) \
    asm volatile("ldmatrix.sync.aligned.m8n8.x4.shared.b16 {%0,%1,%2,%3}, [%4];" \
        : "=r"(a0),"=r"(a1),"=r"(a2),"=r"(a3) : "r"(addr))
#define LDSM_X4_T(a0,a1,a2,a3,addr) \
    asm volatile("ldmatrix.sync.aligned.m8n8.x4.trans.shared.b16 {%0,%1,%2,%3}, [%4];" \
        : "=r"(a0),"=r"(a1),"=r"(a2),"=r"(a3) : "r"(addr))
#define MMA16816(c0,c1,c2,c3,a0,a1,a2,a3,b0,b1) \
    asm volatile("mma.sync.aligned.m16n8k16.row.col.f32.f16.f16.f32 " \
        "{%0,%1,%2,%3}, {%4,%5,%6,%7}, {%8,%9}, {%0,%1,%2,%3};" \
        : "+f"(c0),"+f"(c1),"+f"(c2),"+f"(c3) \
        : "r"(a0),"r"(a1),"r"(a2),"r"(a3),"r"(b0),"r"(b1))
#define CP_ASYNC16(dst, src) \
    asm volatile("cp.async.cg.shared.global [%0], [%1], 16;" :: "r"(dst), "l"(src))
#define CP_COMMIT() asm volatile("cp.async.commit_group;" ::: "memory")
#define CP_WAIT(n)  asm volatile("cp.async.wait_group %0;" :: "n"(n) : "memory")

// ---------------------------------------------------------------------------
// k_setup: blocks 0..31 -> slots/h0 init + zero U,Z,Sx.  block 32 -> P=Wq^T Wk
// ---------------------------------------------------------------------------
__global__ void k_setup(const float* __restrict__ mu, const float* __restrict__ lsig,
                        const float* __restrict__ nslots, const float* __restrict__ nh,
                        const float* __restrict__ Wq, const float* __restrict__ Wk) {
    int blk = blockIdx.x, tid = threadIdx.x;
    if (blk < BB) {
        int b = blk;
        for (int i = tid; i < SS*DD; i += blockDim.x) {
            int d = i & (DD-1);
            float sg = __expf(lsig[d]);
            g_slots[b*SS*DD + i] = mu[d] + sg * nslots[b*SS*DD + i];
            g_U[b*SS*DD + i] = 0.f;
        }
        for (int d = tid; d < DD; d += blockDim.x) {
            float sg = __expf(lsig[d]);
            g_h0[b*DD + d] = mu[d] + sg * nh[b*DD + d];
            g_Sx[b*DD + d] = 0.f;
        }
        if (tid < SS) g_Z[b*SS + tid] = 0.f;
    } else {
        __shared__ float sq[DD*DD], sk[DD*DD];
        for (int i = tid; i < DD*DD; i += blockDim.x) { sq[i] = Wq[i]; sk[i] = Wk[i]; }
        __syncthreads();
        for (int i = tid; i < DD*DD; i += blockDim.x) {
            int dp = i >> 6, d = i & 63;
            float acc = 0.f;
            for (int e = 0; e < DD; e++) acc += sq[e*DD+dp] * sk[e*DD+d];
            g_P[i] = acc;
        }
    }
}

// ---------------------------------------------------------------------------
// k_qp0: q'[b,s,:] = scale * LN_slots(slots[b,s]) @ P
// ---------------------------------------------------------------------------
__global__ void k_qp0(const float* __restrict__ lsg, const float* __restrict__ lsb) {
    int b = blockIdx.x, tid = threadIdx.x;
    __shared__ float sl[SS*DD], sn[SS*DD], m7[SS], r7[SS];
    for (int i = tid; i < SS*DD; i += blockDim.x) sl[i] = g_slots[b*SS*DD+i];
    __syncthreads();
    if (tid < SS) {
        float sm = 0.f, sq = 0.f;
        for (int d = 0; d < DD; d++) { float v = sl[tid*DD+d]; sm += v; sq += v*v; }
        float m = sm * (1.f/DD);
        m7[tid] = m;
        r7[tid] = rsqrtf(sq*(1.f/DD) - m*m + 1e-5f);
    }
    __syncthreads();
    for (int i = tid; i < SS*DD; i += blockDim.x) {
        int s = i >> 6, d = i & 63;
        sn[i] = (sl[i]-m7[s])*r7[s]*lsg[d] + lsb[d];
    }
    __syncthreads();
    for (int o = tid; o < SS*DD; o += blockDim.x) {
        int s = o >> 6, d = o & 63;
        float acc = 0.f;
        for (int dp = 0; dp < DD; dp++) acc += sn[s*DD+dp] * g_P[dp*DD+d];
        g_qp[b*SS*DD+o] = 0.125f * acc;
    }
}

// ---------------------------------------------------------------------------
// k_prep_attn0: fused LN(inputs)->g_xn + iteration-0 attention, with
// double-buffered fp32 input loads (DRAM overlaps LN+GEMMs).
// ---------------------------------------------------------------------------
__global__ __launch_bounds__(TPB)
void k_prep_attn0(const float* __restrict__ x_in,
                  const float* __restrict__ lg, const float* __restrict__ lb) {
    extern __shared__ __align__(16) char smem[];
    uint4*  s_xn4 = (uint4*)(smem + F_XN);       // [128][9]
    __half* s_xnh = (__half*)(smem + F_XN);      // pitch 72 halves
    __half* qph   = (__half*)(smem + F_QPH);     // [8][72]
    __half* pT    = (__half*)(smem + F_PT);      // [8][136]
    float*  part  = (float*)(smem + F_PART);     // [2][64][8]
    float*  s_g   = (float*)(smem + F_G);
    float*  s_b   = (float*)(smem + F_B);

    int b     = blockIdx.x >> 4;                 // CHUNKS_PER_B = 16
    int chunk = blockIdx.x & (CHUNKS_PER_B-1);
    int tid = threadIdx.x;
    int w   = tid >> 5, l = tid & 31;

    long row0 = (long)b*NN + (long)chunk*NT*TILE;
    unsigned in0_sa = (unsigned)__cvta_generic_to_shared(smem + F_IN0);
    unsigned in1_sa = (unsigned)__cvta_generic_to_shared(smem + F_IN1);
    unsigned xn_sa  = (unsigned)__cvta_generic_to_shared(smem + F_XN);

    if (tid < DD) { s_g[tid] = lg[tid]; s_b[tid] = lb[tid]; }
    {
        int n = tid >> 5, kp = tid & 31;
        float2 v = (n < 7) ? ((const float2*)(g_qp + b*SS*DD + n*DD))[kp]
                           : make_float2(0.f, 0.f);
        *(unsigned*)(qph + n*72 + kp*2) = pack_h2(v.x, v.y);
    }

    // issue fp32 tile i -> buffer (i&1): 2048 x 16B chunks
#define ISSUE_IN(i) do { \
        unsigned dstb = ((i) & 1) ? in1_sa : in0_sa; \
        const float4* src = (const float4*)x_in + (row0 + (long)(i)*TILE)*16; \
        _Pragma("unroll") \
        for (int jj = 0; jj < 8; jj++) { \
            int li = jj*256 + tid; \
            unsigned dst = dstb + (unsigned)(((li>>4)*17 + (li&15))*16); \
            CP_ASYNC16(dst, src + li); \
        } \
        CP_COMMIT(); \
    } while (0)

    ISSUE_IN(0);
    ISSUE_IN(1);

    int e   = 2*(l & 3);
    int gid = l >> 2;
    bool lastc = (l & 3) == 3;

    float zacc0 = 0.f, zacc1 = 0.f;
    float u0 = 0.f, u1 = 0.f, u2 = 0.f, u3 = 0.f;
    float sx = 0.f;

    int arow = (l & 15);
    int acol = (l >> 4) << 3;
    int r0p1 = w*16;
    int mt = w & 3, kh = w >> 2;
    int d0 = mt*16;
    int Rr = kh*64;
    int trow = (l & 7) + ((l >> 4) << 3);
    int tcol = ((l >> 3) & 1) << 3;

    for (int i = 0; i < NT; i++) {
        if (i == NT-1) { CP_WAIT(0); } else { CP_WAIT(1); }
        __syncthreads();
        float* s_inf = (float*)(smem + ((i & 1) ? F_IN1 : F_IN0));
        float4* s_in = (float4*)s_inf;

        // ---- LN by 128 threads -> fp16 tile ----
        if (tid < 128) {
            const float4* xr = s_in + tid*17;
            float4 x[16];
#pragma unroll
            for (int j = 0; j < 16; j++) x[j] = xr[j];
            float sm = 0.f, sq = 0.f;
#pragma unroll
            for (int j = 0; j < 16; j++) {
                sm += x[j].x + x[j].y + x[j].z + x[j].w;
                sq += x[j].x*x[j].x + x[j].y*x[j].y + x[j].z*x[j].z + x[j].w*x[j].w;
            }
            float m = sm * (1.f/DD);
            float rstd = rsqrtf(sq*(1.f/DD) - m*m + 1e-5f);
#pragma unroll
            for (int j = 0; j < 8; j++) {
                float4 a = x[2*j], c = x[2*j+1];
                float n0 = (a.x-m)*rstd*s_g[8*j+0] + s_b[8*j+0];
                float n1 = (a.y-m)*rstd*s_g[8*j+1] + s_b[8*j+1];
                float n2 = (a.z-m)*rstd*s_g[8*j+2] + s_b[8*j+2];
                float n3 = (a.w-m)*rstd*s_g[8*j+3] + s_b[8*j+3];
                float n4 = (c.x-m)*rstd*s_g[8*j+4] + s_b[8*j+4];
                float n5 = (c.y-m)*rstd*s_g[8*j+5] + s_b[8*j+5];
                float n6 = (c.z-m)*rstd*s_g[8*j+6] + s_b[8*j+6];
                float n7 = (c.w-m)*rstd*s_g[8*j+7] + s_b[8*j+7];
                uint4 o;
                o.x = pack_h2(n0, n1);
                o.y = pack_h2(n2, n3);
                o.z = pack_h2(n4, n5);
                o.w = pack_h2(n6, n7);
                s_xn4[tid*9 + j] = o;
            }
        }
        __syncthreads();      // in-buffer fully consumed; xn ready

        if (i + 2 < NT) ISSUE_IN(i + 2);

        // ---- write fp16 tile to gmem (coalesced) ----
        {
            uint4* gout = (uint4*)g_xn + (row0 + (long)i*TILE)*8;
#pragma unroll
            for (int jj = 0; jj < 4; jj++) {
                int li = jj*256 + tid;
                gout[li] = s_xn4[(li>>3)*9 + (li&7)];
            }
        }
        // ---- Sx partial ----
        if (tid < DD) {
            float acc = 0.f;
            for (int r = 0; r < TILE; r++) acc += __half2float(s_xnh[r*72 + tid]);
            sx += acc;
        }

        // ---- phase 1: GEMM1 + softmax -> pT ----
        {
            float c0=0.f,c1=0.f,c2=0.f,c3=0.f;
#pragma unroll
            for (int kk = 0; kk < 4; kk++) {
                unsigned addr = xn_sa + (unsigned)(((r0p1 + arow)*72 + kk*16 + acol)*2);
                unsigned a0,a1,a2,a3;
                LDSM_X4(a0,a1,a2,a3, addr);
                unsigned b0 = *(const unsigned*)(qph + gid*72 + kk*16 + e);
                unsigned b1 = *(const unsigned*)(qph + gid*72 + kk*16 + e + 8);
                MMA16816(c0,c1,c2,c3, a0,a1,a2,a3, b0,b1);
            }
            int rA = r0p1 + gid, rB = rA + 8;
            float v1 = lastc ? -1e30f : c1;
            float v3 = lastc ? -1e30f : c3;
            float m0 = fmaxf(c0, v1), m1 = fmaxf(c2, v3);
            m0 = fmaxf(m0, __shfl_xor_sync(0xffffffffu, m0, 1));
            m0 = fmaxf(m0, __shfl_xor_sync(0xffffffffu, m0, 2));
            m1 = fmaxf(m1, __shfl_xor_sync(0xffffffffu, m1, 1));
            m1 = fmaxf(m1, __shfl_xor_sync(0xffffffffu, m1, 2));
            float e0 = __expf(c0 - m0), e1 = lastc ? 0.f : __expf(c1 - m0);
            float e2 = __expf(c2 - m1), e3 = lastc ? 0.f : __expf(c3 - m1);
            float s0 = e0 + e1, s1 = e2 + e3;
            s0 += __shfl_xor_sync(0xffffffffu, s0, 1);
            s0 += __shfl_xor_sync(0xffffffffu, s0, 2);
            s1 += __shfl_xor_sync(0xffffffffu, s1, 1);
            s1 += __shfl_xor_sync(0xffffffffu, s1, 2);
            float p0 = e0/s0, p1 = e1/s0, p2 = e2/s1, p3 = e3/s1;
            pT[e*136 + rA]     = __float2half_rn(p0);
            pT[(e+1)*136 + rA] = __float2half_rn(p1);
            pT[e*136 + rB]     = __float2half_rn(p2);
            pT[(e+1)*136 + rB] = __float2half_rn(p3);
            zacc0 += p0 + p2; zacc1 += p1 + p3;
        }
        __syncthreads();

        // ---- phase 2: GEMM2 accumulate ----
#pragma unroll
        for (int kk = 0; kk < 4; kk++) {
            int k0 = Rr + kk*16;
            unsigned addr = xn_sa + (unsigned)(((k0 + trow)*72 + d0 + tcol)*2);
            unsigned a0,a1,a2,a3;
            LDSM_X4_T(a0,a1,a2,a3, addr);
            unsigned b0 = *(const unsigned*)(pT + gid*136 + k0 + e);
            unsigned b1 = *(const unsigned*)(pT + gid*136 + k0 + e + 8);
            MMA16816(u0,u1,u2,u3, a0,a1,a2,a3, b0,b1);
        }
        __syncthreads();
    }
#undef ISSUE_IN

    // ---- epilogue ----
    if (tid < DD) atomicAdd(&g_Sx[b*DD + tid], sx);
    zacc0 += __shfl_xor_sync(0xffffffffu, zacc0, 4);
    zacc0 += __shfl_xor_sync(0xffffffffu, zacc0, 8);
    zacc0 += __shfl_xor_sync(0xffffffffu, zacc0, 16);
    zacc1 += __shfl_xor_sync(0xffffffffu, zacc1, 4);
    zacc1 += __shfl_xor_sync(0xffffffffu, zacc1, 8);
    zacc1 += __shfl_xor_sync(0xffffffffu, zacc1, 16);
    if (l < 4) {
        atomicAdd(&g_Z[b*SS + 2*l], zacc0);
        if (l < 3) atomicAdd(&g_Z[b*SS + 2*l + 1], zacc1);
    }
    {
        int dim = d0 + gid;
        float2* pp = (float2*)part;
        pp[kh*256 + dim*4 + (e>>1)]     = make_float2(u0, u1);
        pp[kh*256 + (dim+8)*4 + (e>>1)] = make_float2(u2, u3);
    }
    __syncthreads();
#pragma unroll
    for (int i = tid; i < 512; i += TPB) {
        int s = i & 7;
        if (s < 7) {
            int dim = i >> 3;
            float v = part[i] + part[512 + i];
            atomicAdd(&g_U[(b*SS + s)*DD + dim], v);
        }
    }
}

// ---------------------------------------------------------------------------
// k_attn: persistent 8-tile blocks (iterations 1,2) — round-13 version
// ---------------------------------------------------------------------------
__global__ __launch_bounds__(TPB)
void k_attn() {
    extern __shared__ __align__(16) char smem[];
    __half* qph  = (__half*)(smem + A_QPH);     // [8][72]
    __half* pT   = (__half*)(smem + A_PT);      // [8][136]
    float*  part = (float*)(smem + A_PART);     // [2][64][8]

    int b     = blockIdx.x >> 4;
    int chunk = blockIdx.x & (CHUNKS_PER_B-1);
    int tid = threadIdx.x;
    int w   = tid >> 5, l = tid & 31;

    unsigned sbuf0 = (unsigned)__cvta_generic_to_shared(smem + A_XN0);
    unsigned sbuf1 = (unsigned)__cvta_generic_to_shared(smem + A_XN1);
    const uint4* gx = (const uint4*)g_xn + ((long)b*NN + (long)chunk*NT*TILE)*8;

#define ISSUE_TILE(i) do { \
        unsigned dstb = ((i) & 1) ? sbuf1 : sbuf0; \
        const uint4* src = gx + (long)(i)*TILE*8; \
        _Pragma("unroll") \
        for (int jj = 0; jj < 4; jj++) { \
            int li = jj*256 + tid; \
            unsigned dst = dstb + (unsigned)(((li>>3)*9 + (li&7))*16); \
            CP_ASYNC16(dst, src + li); \
        } \
        CP_COMMIT(); \
    } while (0)

    ISSUE_TILE(0);
    ISSUE_TILE(1);

    {
        int n = tid >> 5, kp = tid & 31;
        float2 v = (n < 7) ? ((const float2*)(g_qp + b*SS*DD + n*DD))[kp]
                           : make_float2(0.f, 0.f);
        *(unsigned*)(qph + n*72 + kp*2) = pack_h2(v.x, v.y);
    }

    int e   = 2*(l & 3);
    int gid = l >> 2;
    bool lastc = (l & 3) == 3;

    float zacc0 = 0.f, zacc1 = 0.f;
    float u0 = 0.f, u1 = 0.f, u2 = 0.f, u3 = 0.f;

    int arow = (l & 15);
    int acol = (l >> 4) << 3;
    int r0p1 = w*16;
    int mt = w & 3, kh = w >> 2;
    int d0 = mt*16;
    int Rr = kh*64;
    int trow = (l & 7) + ((l >> 4) << 3);
    int tcol = ((l >> 3) & 1) << 3;

    for (int i = 0; i < NT; i++) {
        if (i == NT-1) { CP_WAIT(0); } else { CP_WAIT(1); }
        __syncthreads();
        unsigned xn_sa = (i & 1) ? sbuf1 : sbuf0;

        {
            float c0=0.f,c1=0.f,c2=0.f,c3=0.f;
#pragma unroll
            for (int kk = 0; kk < 4; kk++) {
                unsigned addr = xn_sa + (unsigned)(((r0p1 + arow)*72 + kk*16 + acol)*2);
                unsigned a0,a1,a2,a3;
                LDSM_X4(a0,a1,a2,a3, addr);
                unsigned b0 = *(const unsigned*)(qph + gid*72 + kk*16 + e);
                unsigned b1 = *(const unsigned*)(qph + gid*72 + kk*16 + e + 8);
                MMA16816(c0,c1,c2,c3, a0,a1,a2,a3, b0,b1);
            }
            int rA = r0p1 + gid, rB = rA + 8;
            float v1 = lastc ? -1e30f : c1;
            float v3 = lastc ? -1e30f : c3;
            float m0 = fmaxf(c0, v1), m1 = fmaxf(c2, v3);
            m0 = fmaxf(m0, __shfl_xor_sync(0xffffffffu, m0, 1));
            m0 = fmaxf(m0, __shfl_xor_sync(0xffffffffu, m0, 2));
            m1 = fmaxf(m1, __shfl_xor_sync(0xffffffffu, m1, 1));
            m1 = fmaxf(m1, __shfl_xor_sync(0xffffffffu, m1, 2));
            float e0 = __expf(c0 - m0), e1 = lastc ? 0.f : __expf(c1 - m0);
            float e2 = __expf(c2 - m1), e3 = lastc ? 0.f : __expf(c3 - m1);
            float s0 = e0 + e1, s1 = e2 + e3;
            s0 += __shfl_xor_sync(0xffffffffu, s0, 1);
            s0 += __shfl_xor_sync(0xffffffffu, s0, 2);
            s1 += __shfl_xor_sync(0xffffffffu, s1, 1);
            s1 += __shfl_xor_sync(0xffffffffu, s1, 2);
            float p0 = e0/s0, p1 = e1/s0, p2 = e2/s1, p3 = e3/s1;
            pT[e*136 + rA]     = __float2half_rn(p0);
            pT[(e+1)*136 + rA] = __float2half_rn(p1);
            pT[e*136 + rB]     = __float2half_rn(p2);
            pT[(e+1)*136 + rB] = __float2half_rn(p3);
            zacc0 += p0 + p2; zacc1 += p1 + p3;
        }
        __syncthreads();

#pragma unroll
        for (int kk = 0; kk < 4; kk++) {
            int k0 = Rr + kk*16;
            unsigned addr = xn_sa + (unsigned)(((k0 + trow)*72 + d0 + tcol)*2);
            unsigned a0,a1,a2,a3;
            LDSM_X4_T(a0,a1,a2,a3, addr);
            unsigned b0 = *(const unsigned*)(pT + gid*136 + k0 + e);
            unsigned b1 = *(const unsigned*)(pT + gid*136 + k0 + e + 8);
            MMA16816(u0,u1,u2,u3, a0,a1,a2,a3, b0,b1);
        }
        __syncthreads();

        if (i + 2 < NT) ISSUE_TILE(i + 2);
    }

    zacc0 += __shfl_xor_sync(0xffffffffu, zacc0, 4);
    zacc0 += __shfl_xor_sync(0xffffffffu, zacc0, 8);
    zacc0 += __shfl_xor_sync(0xffffffffu, zacc0, 16);
    zacc1 += __shfl_xor_sync(0xffffffffu, zacc1, 4);
    zacc1 += __shfl_xor_sync(0xffffffffu, zacc1, 8);
    zacc1 += __shfl_xor_sync(0xffffffffu, zacc1, 16);
    if (l < 4) {
        atomicAdd(&g_Z[b*SS + 2*l], zacc0);
        if (l < 3) atomicAdd(&g_Z[b*SS + 2*l + 1], zacc1);
    }

    {
        int dim = d0 + gid;
        float2* pp = (float2*)part;
        pp[kh*256 + dim*4 + (e>>1)]     = make_float2(u0, u1);
        pp[kh*256 + (dim+8)*4 + (e>>1)] = make_float2(u2, u3);
    }
    __syncthreads();
#pragma unroll
    for (int i = tid; i < 512; i += TPB) {
        int s = i & 7;
        if (s < 7) {
            int dim = i >> 3;
            float v = part[i] + part[512 + i];
            atomicAdd(&g_U[(b*SS + s)*DD + dim], v);
        }
    }
#undef ISSUE_TILE
}

// ---------------------------------------------------------------------------
// k_upd1: per (b,s): supd with 4-thread dots; gi per-thread.
// ---------------------------------------------------------------------------
__global__ __launch_bounds__(256)
void k_upd1(const float* __restrict__ Wv,
            const float* __restrict__ w_ih, const float* __restrict__ b_ih) {
    int blk = blockIdx.x;           // 0..223
    int b = blk / SS, s = blk - b*SS;
    int tid = threadIdx.x;
    __shared__ float sU[DD], supd[DD];
    __shared__ float sZ;

    if (tid < DD) sU[tid] = g_U[(b*SS+s)*DD + tid] + 1e-8f * g_Sx[b*DD + tid];
    if (tid == 0) sZ = g_Z[b*SS+s] + 1.6384e-4f;   // + N*eps
    __syncthreads();

    // supd[o]: 4 threads per output, 16 elements each, shfl merge
    {
        int o = tid >> 2, sub = tid & 3;
        const float4* w = (const float4*)(Wv + o*DD) + sub*4;
        const float4* u = (const float4*)sU + sub*4;
        float a0=0,a1=0,a2=0,a3=0;
#pragma unroll
        for (int j = 0; j < 4; j++) {
            float4 a = u[j], c = w[j];
            a0 += a.x*c.x; a1 += a.y*c.y; a2 += a.z*c.z; a3 += a.w*c.w;
        }
        float acc = (a0+a1)+(a2+a3);
        acc += __shfl_xor_sync(0xffffffffu, acc, 1);
        acc += __shfl_xor_sync(0xffffffffu, acc, 2);
        if (sub == 0) supd[o] = acc / sZ;
    }
    __syncthreads();

    if (tid < 3*DD) {
        const float4* w = (const float4*)(w_ih + tid*DD);
        const float4* u = (const float4*)supd;
        float a0=b_ih[tid],a1=0,a2=0,a3=0;
#pragma unroll
        for (int j = 0; j < 16; j++) {
            float4 a = u[j], c = w[j];
            a0 += a.x*c.x; a1 += a.y*c.y; a2 += a.z*c.z; a3 += a.w*c.w;
        }
        g_gi[(b*SS+s)*3*DD + tid] = (a0+a1)+(a2+a3);
    }
}

// ---------------------------------------------------------------------------
// k_upd2: GRU over slots (whh staged) -> MLP -> slots + next q'
// ---------------------------------------------------------------------------
__global__ __launch_bounds__(256)
void k_upd2(const float* __restrict__ w_hh, const float* __restrict__ b_hh,
            const float* __restrict__ w1, const float* __restrict__ b1,
            const float* __restrict__ w2, const float* __restrict__ b2,
            const float* __restrict__ lsg, const float* __restrict__ lsb,
            const float* __restrict__ lmg, const float* __restrict__ lmb,
            float* __restrict__ dout, int last) {
    extern __shared__ __align__(16) float sm[];
    float* whh = sm + V_WHH;     // [192][68]
    float* gis = sm + V_GI;      // [7][192]
    float* sl  = sm + V_SL;      // [7][64]
    float* xb  = sm + V_XB;
    float* hid = sm + V_HID;     // [7][128]
    float* h   = sm + V_H;
    float* ghs = sm + V_GH;      // [192]
    float* m7  = sm + V_M7;
    float* r7  = sm + V_R7;

    int b = blockIdx.x, tid = threadIdx.x;

    for (int i = tid; i < 3*DD*DD; i += 256) { int r = i>>6, e = i&63; whh[r*68+e] = w_hh[i]; }
    for (int i = tid; i < SS*3*DD; i += 256) gis[i] = g_gi[b*SS*3*DD + i];
    if (tid < DD) h[tid] = g_h0[b*DD+tid];
    __syncthreads();

    for (int s = 0; s < SS; s++) {
        if (tid < 3*DD) {
            const float4* w = (const float4*)(whh + tid*68);
            const float4* hv = (const float4*)h;
            float a0=b_hh[tid],a1=0,a2=0,a3=0;
#pragma unroll
            for (int j = 0; j < 16; j++) {
                float4 c = w[j], a = hv[j];
                a0 += a.x*c.x; a1 += a.y*c.y; a2 += a.z*c.z; a3 += a.w*c.w;
            }
            ghs[tid] = (a0+a1)+(a2+a3);
        }
        __syncthreads();
        if (tid < DD) {
            float r = 1.f/(1.f + __expf(-(gis[s*192+tid]     + ghs[tid])));
            float z = 1.f/(1.f + __expf(-(gis[s*192+64+tid]  + ghs[64+tid])));
            float nx = gis[s*192+128+tid] + r*ghs[128+tid];
            float n = 1.f - 2.f/(__expf(2.f*nx) + 1.f);   // tanh
            float hn = (1.f-z)*n + z*h[tid];
            h[tid] = hn;
            sl[s*DD+tid] = hn;
        }
        __syncthreads();
    }

    if (tid < SS) {
        float smv = 0.f, sq = 0.f;
        for (int d = 0; d < DD; d++) { float v = sl[tid*DD+d]; smv += v; sq += v*v; }
        float m = smv*(1.f/DD);
        m7[tid] = m; r7[tid] = rsqrtf(sq*(1.f/DD) - m*m + 1e-5f);
    }
    __syncthreads();
    for (int i = tid; i < SS*DD; i += 256) {
        int s = i >> 6, d = i & 63;
        xb[i] = (sl[i]-m7[s])*r7[s]*lmg[d] + lmb[d];
    }
    __syncthreads();
    for (int o = tid; o < SS*HH; o += 256) {
        int s = o >> 7, hc = o & 127;
        const float4* w = (const float4*)(w1 + hc*DD);
        const float4* u = (const float4*)(xb + s*DD);
        float a0=b1[hc],a1=0,a2=0,a3=0;
#pragma unroll
        for (int j = 0; j < 16; j++) {
            float4 a = u[j], c = w[j];
            a0 += a.x*c.x; a1 += a.y*c.y; a2 += a.z*c.z; a3 += a.w*c.w;
        }
        hid[o] = fmaxf((a0+a1)+(a2+a3), 0.f);
    }
    __syncthreads();
    for (int o = tid; o < SS*DD; o += 256) {
        int s = o >> 6, d = o & 63;
        const float4* w = (const float4*)(w2 + d*HH);
        const float4* u = (const float4*)(hid + s*HH);
        float a0=b2[d],a1=0,a2=0,a3=0;
#pragma unroll
        for (int j = 0; j < 32; j++) {
            float4 a = u[j], c = w[j];
            a0 += a.x*c.x; a1 += a.y*c.y; a2 += a.z*c.z; a3 += a.w*c.w;
        }
        float v = sl[o] + (a0+a1)+(a2+a3);
        sl[o] = v;
        g_slots[b*SS*DD+o] = v;
        dout[b*SS*DD+o] = v;
    }
    __syncthreads();

    if (!last) {
        if (tid < SS) {
            float smv = 0.f, sq = 0.f;
            for (int d = 0; d < DD; d++) { float v = sl[tid*DD+d]; smv += v; sq += v*v; }
            float m = smv*(1.f/DD);
            m7[tid] = m; r7[tid] = rsqrtf(sq*(1.f/DD) - m*m + 1e-5f);
        }
        __syncthreads();
        for (int i = tid; i < SS*DD; i += 256) {
            int s = i >> 6, d = i & 63;
            xb[i] = (sl[i]-m7[s])*r7[s]*lsg[d] + lsb[d];
        }
        __syncthreads();
        for (int o = tid; o < SS*DD; o += 256) {
            int s = o >> 6, d = o & 63;
            float a0=0,a1=0,a2=0,a3=0;
#pragma unroll
            for (int dp = 0; dp < DD; dp += 4) {
                a0 += xb[s*DD+dp+0]*g_P[(dp+0)*DD+d];
                a1 += xb[s*DD+dp+1]*g_P[(dp+1)*DD+d];
                a2 += xb[s*DD+dp+2]*g_P[(dp+2)*DD+d];
                a3 += xb[s*DD+dp+3]*g_P[(dp+3)*DD+d];
            }
            g_qp[b*SS*DD+o] = 0.125f*((a0+a1)+(a2+a3));
            g_U[b*SS*DD+o] = 0.f;
        }
        if (tid < SS) g_Z[b*SS+tid] = 0.f;
    }
}

// ---------------------------------------------------------------------------
extern "C" void kernel_launch(void* const* d_in, const int* in_sizes, int n_in,
                              void* d_out, int out_size) {
    const float* inputs     = (const float*)d_in[0];
    const float* ln_in_g    = (const float*)d_in[1];
    const float* ln_in_b    = (const float*)d_in[2];
    const float* ln_slots_g = (const float*)d_in[3];
    const float* ln_slots_b = (const float*)d_in[4];
    const float* ln_mlp_g   = (const float*)d_in[5];
    const float* ln_mlp_b   = (const float*)d_in[6];
    const float* Wq         = (const float*)d_in[7];
    const float* Wk         = (const float*)d_in[8];
    const float* Wv         = (const float*)d_in[9];
    const float* mu         = (const float*)d_in[10];
    const float* lsig       = (const float*)d_in[11];
    const float* w_ih       = (const float*)d_in[12];
    const float* w_hh       = (const float*)d_in[13];
    const float* b_ih       = (const float*)d_in[14];
    const float* b_hh       = (const float*)d_in[15];
    const float* w1         = (const float*)d_in[16];
    const float* b1         = (const float*)d_in[17];
    const float* w2         = (const float*)d_in[18];
    const float* b2         = (const float*)d_in[19];
    const float* nslots     = (const float*)d_in[20];
    const float* nh         = (const float*)d_in[21];
    float* out = (float*)d_out;

    cudaFuncSetAttribute(k_prep_attn0, cudaFuncAttributeMaxDynamicSharedMemorySize, FUSED_SMEM_BYTES);
    cudaFuncSetAttribute(k_attn,  cudaFuncAttributeMaxDynamicSharedMemorySize, ATTN_SMEM_BYTES);
    cudaFuncSetAttribute(k_upd2,  cudaFuncAttributeMaxDynamicSharedMemorySize, UPD2_SMEM_BYTES);

    k_setup<<<BB+1, 256>>>(mu, lsig, nslots, nh, Wq, Wk);
    k_qp0<<<BB, 256>>>(ln_slots_g, ln_slots_b);
    k_prep_attn0<<<BB*CHUNKS_PER_B, TPB, FUSED_SMEM_BYTES>>>(inputs, ln_in_g, ln_in_b);
    for (int it = 0; it < 3; it++) {
        if (it > 0) k_attn<<<BB*CHUNKS_PER_B, TPB, ATTN_SMEM_BYTES>>>();
        k_upd1<<<BB*SS, 256>>>(Wv, w_ih, b_ih);
        k_upd2<<<BB, 256, UPD2_SMEM_BYTES>>>(w_hh, b_hh, w1, b1, w2, b2,
                                             ln_slots_g, ln_slots_b, ln_mlp_g, ln_mlp_b,
                                             out, it == 2);
    }
}